// round 6
// baseline (speedup 1.0000x reference)
#include <cuda_runtime.h>
#include <cuda_bf16.h>
#include <math.h>
#include <stdint.h>

#define B_   4
#define N_   8192
#define DIM_ 512
#define H_   8
#define DH_  64
#define BH_  (B_*H_)          // 32
#define MROWS (B_*N_)         // 32768
#define QKVN  (3*DIM_)        // 1536

// ---------------- scratch (device globals; no allocs allowed) ----------------
__device__ float g_q[BH_*N_*DH_];      // [bh][n][d]
__device__ float g_k[BH_*N_*DH_];
__device__ float g_v[BH_*N_*DH_];
__device__ float g_attn[(size_t)MROWS*DIM_];  // fp32 attn output [m][h*64+e]
__device__ float g_ctx[BH_*DH_*DH_];   // [bh][d][e]
__device__ float g_ksum[BH_*DH_];      // [bh][d]
__device__ int   g_maskflags[2];
__device__ int   g_fb[2];              // fallback flags: [0] gemm1, [1] gemm2

// bf16 hi/lo operands, PLAIN ROW-MAJOR, rows of 512 bf16 = 64 uint4
__device__ uint4 Axhi[(size_t)MROWS*64];   // x split         [m][k]
__device__ uint4 Axlo[(size_t)MROWS*64];
__device__ uint4 Bqhi[(size_t)QKVN*64];    // Wqkv^T          [n][k]
__device__ uint4 Bqlo[(size_t)QKVN*64];
__device__ uint4 Athi[(size_t)MROWS*64];   // attn split      [m][h*64+e]
__device__ uint4 Atlo[(size_t)MROWS*64];
__device__ uint4 Bohi[(size_t)DIM_*64];    // Wout^T          [n][k]
__device__ uint4 Bolo[(size_t)DIM_*64];

// ---------------- helpers ----------------
__device__ __forceinline__ uint32_t smem_u32(const void* p) {
    uint32_t a;
    asm("{ .reg .u64 t; cvta.to.shared.u64 t, %1; cvt.u32.u64 %0, t; }" : "=r"(a) : "l"(p));
    return a;
}
__device__ __forceinline__ uint32_t lds32(uint32_t a) {
    uint32_t v;
    asm volatile("ld.shared.b32 %0, [%1];" : "=r"(v) : "r"(a));
    return v;
}
__device__ __forceinline__ uint32_t pack2bf(float a, float b) {
    uint32_t lo = (uint32_t)__bfloat16_as_ushort(__float2bfloat16_rn(a));
    uint32_t hi = (uint32_t)__bfloat16_as_ushort(__float2bfloat16_rn(b));
    return lo | (hi << 16);
}
__device__ __forceinline__ void mma_bf16(float (&d)[4], const uint32_t (&a)[4],
                                         uint32_t b0, uint32_t b1) {
    asm volatile(
        "mma.sync.aligned.m16n8k16.row.col.f32.bf16.bf16.f32 "
        "{%0,%1,%2,%3}, {%4,%5,%6,%7}, {%8,%9}, {%0,%1,%2,%3};"
        : "+f"(d[0]), "+f"(d[1]), "+f"(d[2]), "+f"(d[3])
        : "r"(a[0]), "r"(a[1]), "r"(a[2]), "r"(a[3]), "r"(b0), "r"(b1));
}

// smem tile geometry: 128 rows x 32 bf16, padded row stride 40 bf16 = 80 B.
#define TROWB  80
#define TROWU4 5
#define TILEU4 640
#define TILEB  10240

// =============================================================================
// split kernels: fp32 -> (bf16 hi, bf16 lo), plain row-major
// =============================================================================
__global__ __launch_bounds__(256) void splitX_kernel(const float* __restrict__ x,
                                                     uint4* __restrict__ Ohi,
                                                     uint4* __restrict__ Olo) {
    size_t idx = (size_t)blockIdx.x * 256 + threadIdx.x;
    const float4* xp = (const float4*)x + idx * 2;
    float4 v0 = xp[0], v1 = xp[1];
    float f[8] = {v0.x, v0.y, v0.z, v0.w, v1.x, v1.y, v1.z, v1.w};
    float h[8], l[8];
    #pragma unroll
    for (int j = 0; j < 8; ++j) {
        h[j] = __bfloat162float(__float2bfloat16_rn(f[j]));
        l[j] = f[j] - h[j];
    }
    Ohi[idx] = make_uint4(pack2bf(h[0],h[1]), pack2bf(h[2],h[3]), pack2bf(h[4],h[5]), pack2bf(h[6],h[7]));
    Olo[idx] = make_uint4(pack2bf(l[0],l[1]), pack2bf(l[2],l[3]), pack2bf(l[4],l[5]), pack2bf(l[6],l[7]));
}

__global__ __launch_bounds__(256) void splitW_kernel(const float* __restrict__ W,
                                                     int NW, uint4* __restrict__ Bhi,
                                                     uint4* __restrict__ Blo) {
    int n  = blockIdx.x * 256 + threadIdx.x;
    int k8 = blockIdx.y * 8;
    float f[8], h[8], l[8];
    #pragma unroll
    for (int j = 0; j < 8; ++j) f[j] = W[(size_t)(k8 + j) * NW + n];
    #pragma unroll
    for (int j = 0; j < 8; ++j) {
        h[j] = __bfloat162float(__float2bfloat16_rn(f[j]));
        l[j] = f[j] - h[j];
    }
    size_t o = (size_t)n * 64 + (k8 >> 3);
    Bhi[o] = make_uint4(pack2bf(h[0],h[1]), pack2bf(h[2],h[3]), pack2bf(h[4],h[5]), pack2bf(h[6],h[7]));
    Blo[o] = make_uint4(pack2bf(l[0],l[1]), pack2bf(l[2],l[3]), pack2bf(l[4],l[5]), pack2bf(l[6],l[7]));
}

// =============================================================================
// mma.sync GEMM mainloop (experimental path)
// =============================================================================
__device__ __forceinline__ void mma_mainloop(float (&acc)[2][8][4],
                                             uint4* sm4, uint32_t sb,
                                             const uint4* __restrict__ gA0,
                                             const uint4* __restrict__ gA1,
                                             const uint4* __restrict__ gB0,
                                             const uint4* __restrict__ gB1) {
    const int tid  = threadIdx.x;
    const int lane = tid & 31, wid = tid >> 5;
    const int m0 = (wid & 3) * 32;
    const int n0 = (wid >> 2) * 64;
    const int ly = lane >> 2, lx2 = (lane & 3) * 2;

    const uint32_t sA0 = sb, sA1 = sb + TILEB, sB0 = sb + 2*TILEB, sB1 = sb + 3*TILEB;

    #pragma unroll
    for (int mf = 0; mf < 2; ++mf)
        #pragma unroll
        for (int q = 0; q < 8; ++q)
            #pragma unroll
            for (int j = 0; j < 4; ++j) acc[mf][q][j] = 0.f;

    for (int ch = 0; ch < 16; ++ch) {
        if (ch) __syncthreads();
        #pragma unroll
        for (int i = 0; i < 2; ++i) {
            int o  = tid + i * 256;
            int r  = o >> 2, c8 = o & 3;
            size_t g = (size_t)r * 64 + ch * 4 + c8;
            int    s = r * TROWU4 + c8;
            sm4[s]            = gA0[g];
            sm4[TILEU4   + s] = gA1[g];
            sm4[2*TILEU4 + s] = gB0[g];
            sm4[3*TILEU4 + s] = gB1[g];
        }
        __syncthreads();

        #pragma unroll
        for (int ks = 0; ks < 2; ++ks) {
            const uint32_t kb = (uint32_t)((ks * 16 + lx2) * 2);
            uint32_t ah[2][4], al[2][4];
            #pragma unroll
            for (int mf = 0; mf < 2; ++mf) {
                uint32_t base = (uint32_t)((m0 + mf * 16 + ly) * TROWB) + kb;
                ah[mf][0] = lds32(sA0 + base);
                ah[mf][1] = lds32(sA0 + base + 8 * TROWB);
                ah[mf][2] = lds32(sA0 + base + 16);
                ah[mf][3] = lds32(sA0 + base + 8 * TROWB + 16);
                al[mf][0] = lds32(sA1 + base);
                al[mf][1] = lds32(sA1 + base + 8 * TROWB);
                al[mf][2] = lds32(sA1 + base + 16);
                al[mf][3] = lds32(sA1 + base + 8 * TROWB + 16);
            }
            #pragma unroll
            for (int q = 0; q < 8; ++q) {
                uint32_t bbase = (uint32_t)((n0 + q * 8 + ly) * TROWB) + kb;
                uint32_t b0h = lds32(sB0 + bbase), b1h = lds32(sB0 + bbase + 16);
                uint32_t b0l = lds32(sB1 + bbase), b1l = lds32(sB1 + bbase + 16);
                mma_bf16(acc[0][q], ah[0], b0h, b1h);
                mma_bf16(acc[1][q], ah[1], b0h, b1h);
                mma_bf16(acc[0][q], al[0], b0h, b1h);
                mma_bf16(acc[1][q], al[1], b0h, b1h);
                mma_bf16(acc[0][q], ah[0], b0l, b1l);
                mma_bf16(acc[1][q], ah[1], b0l, b1l);
            }
        }
    }
}

__global__ __launch_bounds__(256) void gemm1_mma() {
    __shared__ uint4 stile[4 * TILEU4];
    uint32_t sb = smem_u32(stile);

    int ntile = blockIdx.x, band = blockIdx.y;
    float acc[2][8][4];
    mma_mainloop(acc, stile, sb,
                 Axhi + (size_t)band * 128 * 64, Axlo + (size_t)band * 128 * 64,
                 Bqhi + (size_t)ntile * 128 * 64, Bqlo + (size_t)ntile * 128 * 64);

    const int lane = threadIdx.x & 31, wid = threadIdx.x >> 5;
    const int m0 = (wid & 3) * 32, n0 = (wid >> 2) * 64;
    const int b  = band >> 6;
    const int gc0 = ntile * 128 + n0;
    const int part = gc0 >> 9;
    const int h    = (gc0 & 511) >> 6;
    float* buf = (part == 0) ? g_q : ((part == 1) ? g_k : g_v);
    float* hbase = buf + (size_t)((b << 3) + h) * N_ * DH_;

    #pragma unroll
    for (int mf = 0; mf < 2; ++mf) {
        #pragma unroll
        for (int hh = 0; hh < 2; ++hh) {
            int n_row = (band & 63) * 128 + m0 + mf * 16 + (lane >> 2) + hh * 8;
            float* rowp = hbase + (size_t)n_row * DH_;
            #pragma unroll
            for (int q = 0; q < 8; ++q) {
                int d = q * 8 + (lane & 3) * 2;
                *(float2*)(rowp + d) = make_float2(acc[mf][q][hh*2], acc[mf][q][hh*2+1]);
            }
        }
    }
}

__global__ __launch_bounds__(256) void gemm2_mma(const float* __restrict__ bias,
                                                 float* __restrict__ out) {
    __shared__ uint4 stile[4 * TILEU4];
    uint32_t sb = smem_u32(stile);

    int ntile = blockIdx.x, band = blockIdx.y;
    float acc[2][8][4];
    mma_mainloop(acc, stile, sb,
                 Athi + (size_t)band * 128 * 64, Atlo + (size_t)band * 128 * 64,
                 Bohi + (size_t)ntile * 128 * 64, Bolo + (size_t)ntile * 128 * 64);

    const int lane = threadIdx.x & 31, wid = threadIdx.x >> 5;
    const int m0 = (wid & 3) * 32, n0 = (wid >> 2) * 64;

    #pragma unroll
    for (int mf = 0; mf < 2; ++mf) {
        #pragma unroll
        for (int hh = 0; hh < 2; ++hh) {
            int m_row = band * 128 + m0 + mf * 16 + (lane >> 2) + hh * 8;
            float* rowp = out + (size_t)m_row * DIM_;
            #pragma unroll
            for (int q = 0; q < 8; ++q) {
                int c = ntile * 128 + n0 + q * 8 + (lane & 3) * 2;
                float2 bv = *(const float2*)(bias + c);
                *(float2*)(rowp + c) = make_float2(acc[mf][q][hh*2]   + bv.x,
                                                   acc[mf][q][hh*2+1] + bv.y);
            }
        }
    }
}

// =============================================================================
// verify kernels: sample 256 outputs, recompute in fp32, set fallback flag.
// NaN-safe: trigger unless diff <= tol.
// =============================================================================
__global__ void verify1_kernel(const float* __restrict__ x, const float* __restrict__ W) {
    int t = threadIdx.x;
    int m = (t * 16411) & (MROWS - 1);
    int c = (t * 613) % QKVN;
    float ref = 0.f;
    const float* xr = x + (size_t)m * DIM_;
    for (int k = 0; k < DIM_; ++k) ref += xr[k] * W[(size_t)k * QKVN + c];
    int part = c >> 9, h = (c & 511) >> 6, d = c & 63;
    int b = m >> 13, n = m & (N_ - 1);
    const float* buf = (part == 0) ? g_q : ((part == 1) ? g_k : g_v);
    float got = buf[((size_t)((b << 3) + h) * N_ + n) * DH_ + d];
    float tol = 1e-2f * fabsf(ref) + 1e-2f;
    if (!(fabsf(got - ref) <= tol)) atomicOr(&g_fb[0], 1);
}

__global__ void verify2_kernel(const float* __restrict__ W, const float* __restrict__ bias,
                               const float* __restrict__ out) {
    int t = threadIdx.x;
    int m = (t * 16411) & (MROWS - 1);
    int c = (t * 613) & (DIM_ - 1);
    float ref = bias[c];
    const float* ar = g_attn + (size_t)m * DIM_;
    for (int k = 0; k < DIM_; ++k) ref += ar[k] * W[(size_t)k * DIM_ + c];
    float got = out[(size_t)m * DIM_ + c];
    float tol = 1e-2f * fabsf(ref) + 1e-2f;
    if (!(fabsf(got - ref) <= tol)) atomicOr(&g_fb[1], 1);
}

// =============================================================================
// FALLBACK fp32 SGEMMs (R1-validated). Early-exit unless flag set.
// =============================================================================
__global__ __launch_bounds__(256) void gemm_qkv_fb(const float* __restrict__ X,
                                                   const float* __restrict__ W) {
    if (g_fb[0] == 0) return;
    const int KD = DIM_, NW = QKVN;
    __shared__ float As[16][132];
    __shared__ float Bs[16][128];

    const int tid   = threadIdx.x;
    const int mBase = blockIdx.y * 128;
    const int nBase = blockIdx.x * 128;

    const int aRow = tid >> 2;
    const int aCol = (tid & 3) << 2;
    const int bRow = tid >> 5;
    const int bCol = (tid & 31) << 2;

    const int ty = tid >> 4, tx = tid & 15;
    const int m0 = ty * 8,  n0 = tx * 8;

    float acc[8][8];
    #pragma unroll
    for (int i = 0; i < 8; ++i)
        #pragma unroll
        for (int j = 0; j < 8; ++j) acc[i][j] = 0.f;

    for (int k0 = 0; k0 < KD; k0 += 16) {
        #pragma unroll
        for (int rr = 0; rr < 128; rr += 64) {
            float4 v = *(const float4*)&X[(size_t)(mBase + aRow + rr) * KD + k0 + aCol];
            As[aCol+0][aRow+rr] = v.x;
            As[aCol+1][aRow+rr] = v.y;
            As[aCol+2][aRow+rr] = v.z;
            As[aCol+3][aRow+rr] = v.w;
        }
        #pragma unroll
        for (int rr = 0; rr < 16; rr += 8) {
            *(float4*)&Bs[bRow+rr][bCol] =
                *(const float4*)&W[(size_t)(k0 + bRow + rr) * NW + nBase + bCol];
        }
        __syncthreads();

        #pragma unroll
        for (int kk = 0; kk < 16; ++kk) {
            float4 a0 = *(float4*)&As[kk][m0];
            float4 a1 = *(float4*)&As[kk][m0+4];
            float4 b0 = *(float4*)&Bs[kk][n0];
            float4 b1 = *(float4*)&Bs[kk][n0+4];
            float ar[8] = {a0.x,a0.y,a0.z,a0.w,a1.x,a1.y,a1.z,a1.w};
            float br[8] = {b0.x,b0.y,b0.z,b0.w,b1.x,b1.y,b1.z,b1.w};
            #pragma unroll
            for (int i = 0; i < 8; ++i)
                #pragma unroll
                for (int j = 0; j < 8; ++j)
                    acc[i][j] += ar[i] * br[j];
        }
        __syncthreads();
    }

    const int part    = nBase >> 9;
    const int rembase = nBase & 511;
    float* dstbuf = (part == 0) ? g_q : ((part == 1) ? g_k : g_v);

    #pragma unroll
    for (int i = 0; i < 8; ++i) {
        int gm = mBase + m0 + i;
        int b  = gm >> 13;
        int n  = gm & (N_-1);
        #pragma unroll
        for (int j = 0; j < 8; ++j) {
            int rem = rembase + n0 + j;
            int h = rem >> 6, d = rem & 63;
            dstbuf[(size_t)(((b << 3) + h) * N_ + n) * DH_ + d] = acc[i][j];
        }
    }
}

__global__ __launch_bounds__(256) void gemm_out_fb(const float* __restrict__ W,
                                                   const float* __restrict__ bias,
                                                   float* __restrict__ out) {
    if (g_fb[1] == 0) return;
    const int KD = DIM_, NW = DIM_;
    __shared__ float As[16][132];
    __shared__ float Bs[16][128];

    const int tid   = threadIdx.x;
    const int mBase = blockIdx.y * 128;
    const int nBase = blockIdx.x * 128;

    const int aRow = tid >> 2;
    const int aCol = (tid & 3) << 2;
    const int bRow = tid >> 5;
    const int bCol = (tid & 31) << 2;

    const int ty = tid >> 4, tx = tid & 15;
    const int m0 = ty * 8,  n0 = tx * 8;

    float acc[8][8];
    #pragma unroll
    for (int i = 0; i < 8; ++i)
        #pragma unroll
        for (int j = 0; j < 8; ++j) acc[i][j] = 0.f;

    for (int k0 = 0; k0 < KD; k0 += 16) {
        #pragma unroll
        for (int rr = 0; rr < 128; rr += 64) {
            float4 v = *(const float4*)&g_attn[(size_t)(mBase + aRow + rr) * KD + k0 + aCol];
            As[aCol+0][aRow+rr] = v.x;
            As[aCol+1][aRow+rr] = v.y;
            As[aCol+2][aRow+rr] = v.z;
            As[aCol+3][aRow+rr] = v.w;
        }
        #pragma unroll
        for (int rr = 0; rr < 16; rr += 8) {
            *(float4*)&Bs[bRow+rr][bCol] =
                *(const float4*)&W[(size_t)(k0 + bRow + rr) * NW + nBase + bCol];
        }
        __syncthreads();

        #pragma unroll
        for (int kk = 0; kk < 16; ++kk) {
            float4 a0 = *(float4*)&As[kk][m0];
            float4 a1 = *(float4*)&As[kk][m0+4];
            float4 b0 = *(float4*)&Bs[kk][n0];
            float4 b1 = *(float4*)&Bs[kk][n0+4];
            float ar[8] = {a0.x,a0.y,a0.z,a0.w,a1.x,a1.y,a1.z,a1.w};
            float br[8] = {b0.x,b0.y,b0.z,b0.w,b1.x,b1.y,b1.z,b1.w};
            #pragma unroll
            for (int i = 0; i < 8; ++i)
                #pragma unroll
                for (int j = 0; j < 8; ++j)
                    acc[i][j] += ar[i] * br[j];
        }
        __syncthreads();
    }

    #pragma unroll
    for (int i = 0; i < 8; ++i) {
        int gm = mBase + m0 + i;
        #pragma unroll
        for (int j = 0; j < 8; j += 4) {
            int gn = nBase + n0 + j;
            float4 bv = *(const float4*)&bias[gn];
            float4 o = make_float4(acc[i][j] + bv.x, acc[i][j+1] + bv.y,
                                   acc[i][j+2] + bv.z, acc[i][j+3] + bv.w);
            *(float4*)&out[(size_t)gm * NW + gn] = o;
        }
    }
}

// =============================================================================
// elementwise chain (R1-validated)
// =============================================================================
__global__ __launch_bounds__(256) void qsoftmax_kernel() {
    const float SCALE = 0.125f;
    int gwarp = (blockIdx.x * 256 + threadIdx.x) >> 5;
    int lane  = threadIdx.x & 31;
    float2 v = *(const float2*)&g_q[(size_t)gwarp * 64 + lane * 2];
    float a = v.x * SCALE, b = v.y * SCALE;
    float mx = fmaxf(a, b);
    #pragma unroll
    for (int off = 16; off > 0; off >>= 1)
        mx = fmaxf(mx, __shfl_xor_sync(0xffffffff, mx, off));
    float ea = __expf(a - mx), eb = __expf(b - mx);
    float s = ea + eb;
    #pragma unroll
    for (int off = 16; off > 0; off >>= 1)
        s += __shfl_xor_sync(0xffffffff, s, off);
    float inv = 1.f / s;
    *(float2*)&g_q[(size_t)gwarp * 64 + lane * 2] = make_float2(ea * inv, eb * inv);
}

__global__ __launch_bounds__(256) void ksum_kernel() {
    int bh = blockIdx.x, chunk = blockIdx.y;
    int t = threadIdx.x;
    int d = t & 63, g = t >> 6;
    const float* kp = g_k + (size_t)bh * N_ * DH_;
    int nb = chunk * 1024 + g * 256;
    float s = 0.f;
    #pragma unroll 8
    for (int i = 0; i < 256; ++i)
        s += __expf(kp[(size_t)(nb + i) * DH_ + d]);
    __shared__ float red[4][64];
    red[g][d] = s;
    __syncthreads();
    if (g == 0)
        atomicAdd(&g_ksum[bh * DH_ + d], red[0][d] + red[1][d] + red[2][d] + red[3][d]);
}

__global__ __launch_bounds__(256) void detect_mask_kernel(const unsigned char* __restrict__ m) {
    int i = blockIdx.x * 256 + threadIdx.x;
    uchar4 v = ((const uchar4*)m)[i];
    bool f32sig = (v.w == 0x3f);
    bool offnz  = (v.y | v.z | v.w) != 0;
    unsigned b1 = __ballot_sync(0xffffffff, f32sig);
    unsigned b2 = __ballot_sync(0xffffffff, offnz);
    if ((threadIdx.x & 31) == 0) {
        if (b1) atomicOr(&g_maskflags[0], 1);
        if (b2) atomicOr(&g_maskflags[1], 1);
    }
}

__global__ __launch_bounds__(256) void knorm_kernel(const void* __restrict__ mask) {
    int i4  = blockIdx.x * 256 + threadIdx.x;
    int idx = i4 << 2;
    int row = idx >> 6;
    int d   = idx & 63;
    int bh  = row >> 13;

    int f32f = g_maskflags[0], u8f = g_maskflags[1];
    bool mz;
    if (f32f)      mz = ((const float*)mask)[row] != 0.f;
    else if (u8f)  mz = ((const unsigned char*)mask)[row] != 0;
    else           mz = ((const int*)mask)[row] != 0;

    float4 kv = *(const float4*)&g_k[idx];
    float4 o;
    if (mz) {
        o = make_float4(0.f, 0.f, 0.f, 0.f);
    } else {
        float4 sv = *(const float4*)&g_ksum[(bh << 6) + d];
        o.x = __expf(kv.x) / sv.x;
        o.y = __expf(kv.y) / sv.y;
        o.z = __expf(kv.z) / sv.z;
        o.w = __expf(kv.w) / sv.w;
    }
    *(float4*)&g_k[idx] = o;
}

__global__ __launch_bounds__(256) void ctx_kernel() {
    int bh = blockIdx.x, chunk = blockIdx.y;
    __shared__ float qs[32][64];
    __shared__ float ks[32][64];
    int t = threadIdx.x;
    int d0 = (t >> 4) << 2, e0 = (t & 15) << 2;
    int lr = t >> 3, lc = (t & 7) << 3;

    const float* qp = g_q + (size_t)(bh * N_ + chunk * 1024) * DH_;
    const float* kp = g_k + (size_t)(bh * N_ + chunk * 1024) * DH_;

    float acc[4][4];
    #pragma unroll
    for (int i = 0; i < 4; ++i)
        #pragma unroll
        for (int j = 0; j < 4; ++j) acc[i][j] = 0.f;

    for (int it = 0; it < 32; ++it) {
        size_t base = (size_t)it * 32 * 64 + (size_t)lr * 64 + lc;
        *(float4*)&qs[lr][lc]   = *(const float4*)&qp[base];
        *(float4*)&qs[lr][lc+4] = *(const float4*)&qp[base + 4];
        *(float4*)&ks[lr][lc]   = *(const float4*)&kp[base];
        *(float4*)&ks[lr][lc+4] = *(const float4*)&kp[base + 4];
        __syncthreads();
        #pragma unroll
        for (int n = 0; n < 32; ++n) {
            float4 qa = *(float4*)&qs[n][d0];
            float4 ka = *(float4*)&ks[n][e0];
            float qr[4] = {qa.x,qa.y,qa.z,qa.w};
            float kr[4] = {ka.x,ka.y,ka.z,ka.w};
            #pragma unroll
            for (int i = 0; i < 4; ++i)
                #pragma unroll
                for (int j = 0; j < 4; ++j)
                    acc[i][j] += qr[i] * kr[j];
        }
        __syncthreads();
    }
    #pragma unroll
    for (int i = 0; i < 4; ++i)
        #pragma unroll
        for (int j = 0; j < 4; ++j)
            atomicAdd(&g_ctx[bh * 4096 + (d0 + i) * 64 + (e0 + j)], acc[i][j]);
}

// attn: write fp32 g_attn (fallback input) + bf16 hi/lo rows (mma gemm2 input)
__global__ __launch_bounds__(256) void attn_out_kernel() {
    int bh = blockIdx.x, chunk = blockIdx.y;
    __shared__ float cs[64][64];
    __shared__ float vs[64][64];
    int t = threadIdx.x;

    const float* cp = g_ctx + bh * 4096;
    const float* vp = g_v + (size_t)(bh * N_ + chunk * 64) * DH_;
    #pragma unroll
    for (int u = 0; u < 4; ++u) {
        ((float4*)cs)[u * 256 + t] = ((const float4*)cp)[u * 256 + t];
        ((float4*)vs)[u * 256 + t] = ((const float4*)vp)[u * 256 + t];
    }
    __syncthreads();

    int r64 = t >> 2;
    int e1 = (t & 3) << 4;
    float acc[16];
    #pragma unroll
    for (int j = 0; j < 16; ++j) acc[j] = 0.f;

    #pragma unroll
    for (int dd = 0; dd < 64; ++dd) {
        float vv = vs[r64][dd];
        #pragma unroll
        for (int j = 0; j < 16; ++j)
            acc[j] += vv * cs[dd][e1 + j];
    }

    int b = bh >> 3, h = bh & 7;
    size_t m = (size_t)b * N_ + chunk * 64 + r64;     // global attn row
    float* fdst = g_attn + m * DIM_ + h * 64 + e1;
    #pragma unroll
    for (int u = 0; u < 4; ++u)
        *(float4*)(fdst + u * 4) = make_float4(acc[u*4+0], acc[u*4+1], acc[u*4+2], acc[u*4+3]);

    #pragma unroll
    for (int u = 0; u < 2; ++u) {
        float hi[8], lo[8];
        #pragma unroll
        for (int j = 0; j < 8; ++j) {
            float v = acc[u * 8 + j];
            hi[j] = __bfloat162float(__float2bfloat16_rn(v));
            lo[j] = v - hi[j];
        }
        size_t o = m * 64 + ((h * 64 + e1 + u * 8) >> 3);
        Athi[o] = make_uint4(pack2bf(hi[0],hi[1]), pack2bf(hi[2],hi[3]),
                             pack2bf(hi[4],hi[5]), pack2bf(hi[6],hi[7]));
        Atlo[o] = make_uint4(pack2bf(lo[0],lo[1]), pack2bf(lo[2],lo[3]),
                             pack2bf(lo[4],lo[5]), pack2bf(lo[6],lo[7]));
    }
}

// =============================================================================
extern "C" void kernel_launch(void* const* d_in, const int* in_sizes, int n_in,
                              void* d_out, int out_size) {
    const float* x    = (const float*)d_in[0];
    const void*  mask = d_in[1];
    const float* Wqkv = (const float*)d_in[2];
    const float* Wout = (const float*)d_in[3];
    const float* bout = (const float*)d_in[4];
    float* out = (float*)d_out;

    void *pks, *pctx, *pfl, *pfb;
    cudaGetSymbolAddress(&pks,  g_ksum);
    cudaGetSymbolAddress(&pctx, g_ctx);
    cudaGetSymbolAddress(&pfl,  g_maskflags);
    cudaGetSymbolAddress(&pfb,  g_fb);
    cudaMemsetAsync(pks,  0, sizeof(float) * BH_ * DH_);
    cudaMemsetAsync(pctx, 0, sizeof(float) * BH_ * DH_ * DH_);
    cudaMemsetAsync(pfl,  0, 2 * sizeof(int));
    cudaMemsetAsync(pfb,  0, 2 * sizeof(int));

    // operand splits for the mma path
    splitX_kernel<<<(MROWS * 64) / 256, 256>>>(x, Axhi, Axlo);
    splitW_kernel<<<dim3(QKVN / 256, DIM_ / 8), 256>>>(Wqkv, QKVN, Bqhi, Bqlo);
    splitW_kernel<<<dim3(DIM_ / 256, DIM_ / 8), 256>>>(Wout, DIM_, Bohi, Bolo);

    // GEMM1: mma attempt -> verify -> conditional fp32 fallback
    gemm1_mma<<<dim3(QKVN / 128, MROWS / 128), 256>>>();
    verify1_kernel<<<1, 256>>>(x, Wqkv);
    gemm_qkv_fb<<<dim3(QKVN / 128, MROWS / 128), 256>>>(x, Wqkv);

    // elementwise chain
    qsoftmax_kernel<<<(BH_ * N_) / 8, 256>>>();
    ksum_kernel<<<dim3(BH_, 8), 256>>>();
    detect_mask_kernel<<<(BH_ * N_) / 1024, 256>>>((const unsigned char*)mask);
    knorm_kernel<<<(BH_ * N_ * DH_) / 1024, 256>>>(mask);
    ctx_kernel<<<dim3(BH_, 8), 256>>>();
    attn_out_kernel<<<dim3(BH_, N_ / 64), 256>>>();

    // GEMM2: mma attempt -> verify -> conditional fp32 fallback
    gemm2_mma<<<dim3(DIM_ / 128, MROWS / 128), 256>>>(bout, out);
    verify2_kernel<<<1, 256>>>(Wout, bout, out);
    gemm_out_fb<<<dim3(DIM_ / 128, MROWS / 128), 256>>>(Wout, bout, out);
}

// round 7
// speedup vs baseline: 1.7038x; 1.7038x over previous
#include <cuda_runtime.h>
#include <math.h>
#include <stdint.h>

#define B_   4
#define N_   8192
#define DIM_ 512
#define H_   8
#define DH_  64
#define BH_  (B_*H_)          // 32
#define MROWS (B_*N_)         // 32768
#define QKVN  (3*DIM_)        // 1536

// ---------------- scratch (device globals; no allocs allowed) ----------------
__device__ float g_q[BH_*N_*DH_];      // [bh][n][d]
__device__ float g_k[BH_*N_*DH_];
__device__ float g_v[BH_*N_*DH_];
__device__ float g_attn[(size_t)MROWS*DIM_];  // [m][h*64+e]
__device__ float g_ctx[BH_*DH_*DH_];   // [bh][d][e]
__device__ float g_ksum[BH_*DH_];      // [bh][d]
__device__ int   g_maskflags[2];

// ---------------- helpers ----------------
__device__ __forceinline__ uint32_t smem_u32(const void* p) {
    uint32_t a;
    asm("{ .reg .u64 t; cvta.to.shared.u64 t, %1; cvt.u32.u64 %0, t; }" : "=r"(a) : "l"(p));
    return a;
}
__device__ __forceinline__ void cp16(uint32_t dst, const void* src) {
    asm volatile("cp.async.ca.shared.global [%0], [%1], 16;" :: "r"(dst), "l"(src));
}
__device__ __forceinline__ void cp_commit() {
    asm volatile("cp.async.commit_group;" ::: "memory");
}
template<int N> __device__ __forceinline__ void cp_wait() {
    asm volatile("cp.async.wait_group %0;" :: "n"(N) : "memory");
}

// smem geometry: A stage = 128 rows x (16 floats + 4 pad) = 128*80 = 10240 B
//                B stage = 16 rows x (128 floats + 4 pad)  = 16*528 =  8448 B
// two stages each: A at [0, 20480), B at [20480, 37376). 37376 B static.
#define A_STAGE 10240
#define B_BASE  20480
#define B_STAGE 8448
#define SMEM_TOT 37376

// =============================================================================
// cp.async double-buffered fp32 mainloop: C[128,128] over K=512 (32 stages of 16)
// 256 threads (16x16), 8x8 outputs per thread.
// =============================================================================
__device__ __forceinline__ void gemm_mainloop(float (&acc)[8][8], char* sm, uint32_t sb,
                                              const float* __restrict__ Ag,
                                              const float* __restrict__ Bg, int NW) {
    const int tid = threadIdx.x;
    const int ty = tid >> 4, tx = tid & 15;
    const int m0 = ty * 8;

    #pragma unroll
    for (int i = 0; i < 8; ++i)
        #pragma unroll
        for (int j = 0; j < 8; ++j) acc[i][j] = 0.f;

    const int ar_ = tid >> 2,  ac_ = tid & 3;     // A: 512 chunks/stage, 2 per thread
    const int br_ = tid >> 5,  bc_ = tid & 31;    // B: 512 chunks/stage, 2 per thread

    // stage issue: A rows 128 x 64B (4 chunks), B rows 16 x 512B (32 chunks)
    auto issue = [&](int ch, int p) {
        uint32_t Ab = sb + p * A_STAGE;
        uint32_t Bb = sb + B_BASE + p * B_STAGE;
        #pragma unroll
        for (int i = 0; i < 2; ++i) {
            int r = ar_ + i * 64;                      // 0..127
            cp16(Ab + r * 80 + ac_ * 16,
                 Ag + (size_t)r * DIM_ + ch * 16 + ac_ * 4);
        }
        #pragma unroll
        for (int i = 0; i < 2; ++i) {
            int r = br_ + i * 8;                       // 0..15
            cp16(Bb + r * 528 + bc_ * 16,
                 Bg + (size_t)(ch * 16 + r) * NW + bc_ * 4);
        }
    };

    issue(0, 0);
    cp_commit();

    #pragma unroll 1
    for (int ch = 0; ch < 32; ++ch) {
        int p = ch & 1;
        if (ch < 31) {
            issue(ch + 1, p ^ 1);
            cp_commit();
            cp_wait<1>();
        } else {
            cp_wait<0>();
        }
        __syncthreads();

        const float* As = (const float*)(sm + p * A_STAGE);
        const char*  Bs = sm + B_BASE + p * B_STAGE;

        #pragma unroll
        for (int kk = 0; kk < 16; ++kk) {
            float4 b0 = *(const float4*)(Bs + kk * 528 + tx * 32);
            float4 b1 = *(const float4*)(Bs + kk * 528 + tx * 32 + 16);
            float br[8] = {b0.x, b0.y, b0.z, b0.w, b1.x, b1.y, b1.z, b1.w};
            float ar[8];
            #pragma unroll
            for (int i = 0; i < 8; ++i) ar[i] = As[(m0 + i) * 20 + kk];
            #pragma unroll
            for (int i = 0; i < 8; ++i)
                #pragma unroll
                for (int j = 0; j < 8; ++j)
                    acc[i][j] += ar[i] * br[j];
        }
        __syncthreads();
    }
}

// GEMM1: qkv = X @ Wqkv -> scatter into g_q/g_k/g_v
__global__ __launch_bounds__(256, 2) void gemm1_cp(const float* __restrict__ X,
                                                   const float* __restrict__ W) {
    __shared__ __align__(16) char sm[SMEM_TOT];
    uint32_t sb = smem_u32(sm);

    const int nBase = blockIdx.x * 128;
    const int mBase = blockIdx.y * 128;

    float acc[8][8];
    gemm_mainloop(acc, sm, sb, X + (size_t)mBase * DIM_, W + nBase, QKVN);

    const int tid = threadIdx.x;
    const int ty = tid >> 4, tx = tid & 15;
    const int m0 = ty * 8, n0 = tx * 8;

    const int part    = nBase >> 9;        // 128-tiles never cross 512 boundaries
    const int rembase = nBase & 511;
    float* dstbuf = (part == 0) ? g_q : ((part == 1) ? g_k : g_v);

    #pragma unroll
    for (int i = 0; i < 8; ++i) {
        int gm = mBase + m0 + i;
        int b  = gm >> 13;
        int n  = gm & (N_ - 1);
        #pragma unroll
        for (int j = 0; j < 8; ++j) {
            int rem = rembase + n0 + j;
            int h = rem >> 6, d = rem & 63;
            dstbuf[(size_t)(((b << 3) + h) * N_ + n) * DH_ + d] = acc[i][j];
        }
    }
}

// GEMM2: out = g_attn @ Wout + bout
__global__ __launch_bounds__(256, 2) void gemm2_cp(const float* __restrict__ W,
                                                   const float* __restrict__ bias,
                                                   float* __restrict__ out) {
    __shared__ __align__(16) char sm[SMEM_TOT];
    uint32_t sb = smem_u32(sm);

    const int nBase = blockIdx.x * 128;
    const int mBase = blockIdx.y * 128;

    float acc[8][8];
    gemm_mainloop(acc, sm, sb, g_attn + (size_t)mBase * DIM_, W + nBase, DIM_);

    const int tid = threadIdx.x;
    const int ty = tid >> 4, tx = tid & 15;
    const int m0 = ty * 8, n0 = tx * 8;

    #pragma unroll
    for (int i = 0; i < 8; ++i) {
        int gm = mBase + m0 + i;
        #pragma unroll
        for (int j = 0; j < 8; j += 4) {
            int gn = nBase + n0 + j;
            float4 bv = *(const float4*)&bias[gn];
            float4 o = make_float4(acc[i][j] + bv.x, acc[i][j+1] + bv.y,
                                   acc[i][j+2] + bv.z, acc[i][j+3] + bv.w);
            *(float4*)&out[(size_t)gm * DIM_ + gn] = o;
        }
    }
}

// =============================================================================
// q softmax over feature dim d=64 (after *SCALE). One warp per row.
// =============================================================================
__global__ __launch_bounds__(256) void qsoftmax_kernel() {
    const float SCALE = 0.125f;
    int gwarp = (blockIdx.x * 256 + threadIdx.x) >> 5;
    int lane  = threadIdx.x & 31;
    float2 v = *(const float2*)&g_q[(size_t)gwarp * 64 + lane * 2];
    float a = v.x * SCALE, b = v.y * SCALE;
    float mx = fmaxf(a, b);
    #pragma unroll
    for (int off = 16; off > 0; off >>= 1)
        mx = fmaxf(mx, __shfl_xor_sync(0xffffffff, mx, off));
    float ea = __expf(a - mx), eb = __expf(b - mx);
    float s = ea + eb;
    #pragma unroll
    for (int off = 16; off > 0; off >>= 1)
        s += __shfl_xor_sync(0xffffffff, s, off);
    float inv = 1.f / s;
    *(float2*)&g_q[(size_t)gwarp * 64 + lane * 2] = make_float2(ea * inv, eb * inv);
}

// =============================================================================
// k softmax over n: pass 1 — partial sums of exp(k) per (bh,d).
// =============================================================================
__global__ __launch_bounds__(256) void ksum_kernel() {
    int bh = blockIdx.x, chunk = blockIdx.y;
    int t = threadIdx.x;
    int d = t & 63, g = t >> 6;
    const float* kp = g_k + (size_t)bh * N_ * DH_;
    int nb = chunk * 1024 + g * 256;
    float s = 0.f;
    #pragma unroll 8
    for (int i = 0; i < 256; ++i)
        s += __expf(kp[(size_t)(nb + i) * DH_ + d]);
    __shared__ float red[4][64];
    red[g][d] = s;
    __syncthreads();
    if (g == 0)
        atomicAdd(&g_ksum[bh * DH_ + d], red[0][d] + red[1][d] + red[2][d] + red[3][d]);
}

// =============================================================================
// Mask dtype detection (bool may be serialized as u8 / i32 / f32).
// =============================================================================
__global__ __launch_bounds__(256) void detect_mask_kernel(const unsigned char* __restrict__ m) {
    int i = blockIdx.x * 256 + threadIdx.x;
    uchar4 v = ((const uchar4*)m)[i];
    bool f32sig = (v.w == 0x3f);
    bool offnz  = (v.y | v.z | v.w) != 0;
    unsigned b1 = __ballot_sync(0xffffffff, f32sig);
    unsigned b2 = __ballot_sync(0xffffffff, offnz);
    if ((threadIdx.x & 31) == 0) {
        if (b1) atomicOr(&g_maskflags[0], 1);
        if (b2) atomicOr(&g_maskflags[1], 1);
    }
}

// =============================================================================
// k softmax pass 2: k = mask ? 0 : exp(k)/sum.
// =============================================================================
__global__ __launch_bounds__(256) void knorm_kernel(const void* __restrict__ mask) {
    int i4  = blockIdx.x * 256 + threadIdx.x;
    int idx = i4 << 2;
    int row = idx >> 6;
    int d   = idx & 63;
    int bh  = row >> 13;

    int f32f = g_maskflags[0], u8f = g_maskflags[1];
    bool mz;
    if (f32f)      mz = ((const float*)mask)[row] != 0.f;
    else if (u8f)  mz = ((const unsigned char*)mask)[row] != 0;
    else           mz = ((const int*)mask)[row] != 0;

    float4 kv = *(const float4*)&g_k[idx];
    float4 o;
    if (mz) {
        o = make_float4(0.f, 0.f, 0.f, 0.f);
    } else {
        float4 sv = *(const float4*)&g_ksum[(bh << 6) + d];
        o.x = __expf(kv.x) / sv.x;
        o.y = __expf(kv.y) / sv.y;
        o.z = __expf(kv.z) / sv.z;
        o.w = __expf(kv.w) / sv.w;
    }
    *(float4*)&g_k[idx] = o;
}

// =============================================================================
// context[bh][d][e] += sum_n q[n,d]*k[n,e]
// =============================================================================
__global__ __launch_bounds__(256) void ctx_kernel() {
    int bh = blockIdx.x, chunk = blockIdx.y;
    __shared__ float qs[32][64];
    __shared__ float ks[32][64];
    int t = threadIdx.x;
    int d0 = (t >> 4) << 2, e0 = (t & 15) << 2;
    int lr = t >> 3, lc = (t & 7) << 3;

    const float* qp = g_q + (size_t)(bh * N_ + chunk * 1024) * DH_;
    const float* kp = g_k + (size_t)(bh * N_ + chunk * 1024) * DH_;

    float acc[4][4];
    #pragma unroll
    for (int i = 0; i < 4; ++i)
        #pragma unroll
        for (int j = 0; j < 4; ++j) acc[i][j] = 0.f;

    for (int it = 0; it < 32; ++it) {
        size_t base = (size_t)it * 32 * 64 + (size_t)lr * 64 + lc;
        *(float4*)&qs[lr][lc]   = *(const float4*)&qp[base];
        *(float4*)&qs[lr][lc+4] = *(const float4*)&qp[base + 4];
        *(float4*)&ks[lr][lc]   = *(const float4*)&kp[base];
        *(float4*)&ks[lr][lc+4] = *(const float4*)&kp[base + 4];
        __syncthreads();
        #pragma unroll
        for (int n = 0; n < 32; ++n) {
            float4 qa = *(float4*)&qs[n][d0];
            float4 ka = *(float4*)&ks[n][e0];
            float qr[4] = {qa.x,qa.y,qa.z,qa.w};
            float kr[4] = {ka.x,ka.y,ka.z,ka.w};
            #pragma unroll
            for (int i = 0; i < 4; ++i)
                #pragma unroll
                for (int j = 0; j < 4; ++j)
                    acc[i][j] += qr[i] * kr[j];
        }
        __syncthreads();
    }
    #pragma unroll
    for (int i = 0; i < 4; ++i)
        #pragma unroll
        for (int j = 0; j < 4; ++j)
            atomicAdd(&g_ctx[bh * 4096 + (d0 + i) * 64 + (e0 + j)], acc[i][j]);
}

// =============================================================================
// attn[m][h*64+e] = sum_d v[n,d]*ctx[d,e] (fp32)
// =============================================================================
__global__ __launch_bounds__(256) void attn_out_kernel() {
    int bh = blockIdx.x, chunk = blockIdx.y;
    __shared__ float cs[64][64];
    __shared__ float vs[64][64];
    int t = threadIdx.x;

    const float* cp = g_ctx + bh * 4096;
    const float* vp = g_v + (size_t)(bh * N_ + chunk * 64) * DH_;
    #pragma unroll
    for (int u = 0; u < 4; ++u) {
        ((float4*)cs)[u * 256 + t] = ((const float4*)cp)[u * 256 + t];
        ((float4*)vs)[u * 256 + t] = ((const float4*)vp)[u * 256 + t];
    }
    __syncthreads();

    int r64 = t >> 2;
    int e1 = (t & 3) << 4;
    float acc[16];
    #pragma unroll
    for (int j = 0; j < 16; ++j) acc[j] = 0.f;

    #pragma unroll
    for (int dd = 0; dd < 64; ++dd) {
        float vv = vs[r64][dd];
        #pragma unroll
        for (int j = 0; j < 16; ++j)
            acc[j] += vv * cs[dd][e1 + j];
    }

    int b = bh >> 3, h = bh & 7;
    size_t m = (size_t)b * N_ + chunk * 64 + r64;
    float* fdst = g_attn + m * DIM_ + h * 64 + e1;
    #pragma unroll
    for (int u = 0; u < 4; ++u)
        *(float4*)(fdst + u * 4) = make_float4(acc[u*4+0], acc[u*4+1], acc[u*4+2], acc[u*4+3]);
}

// =============================================================================
extern "C" void kernel_launch(void* const* d_in, const int* in_sizes, int n_in,
                              void* d_out, int out_size) {
    const float* x    = (const float*)d_in[0];
    const void*  mask = d_in[1];
    const float* Wqkv = (const float*)d_in[2];
    const float* Wout = (const float*)d_in[3];
    const float* bout = (const float*)d_in[4];
    float* out = (float*)d_out;

    void *pks, *pctx, *pfl;
    cudaGetSymbolAddress(&pks,  g_ksum);
    cudaGetSymbolAddress(&pctx, g_ctx);
    cudaGetSymbolAddress(&pfl,  g_maskflags);
    cudaMemsetAsync(pks,  0, sizeof(float) * BH_ * DH_);
    cudaMemsetAsync(pctx, 0, sizeof(float) * BH_ * DH_ * DH_);
    cudaMemsetAsync(pfl,  0, 2 * sizeof(int));

    gemm1_cp<<<dim3(QKVN / 128, MROWS / 128), 256>>>(x, Wqkv);

    qsoftmax_kernel<<<(BH_ * N_) / 8, 256>>>();
    ksum_kernel<<<dim3(BH_, 8), 256>>>();
    detect_mask_kernel<<<(BH_ * N_) / 1024, 256>>>((const unsigned char*)mask);
    knorm_kernel<<<(BH_ * N_ * DH_) / 1024, 256>>>(mask);
    ctx_kernel<<<dim3(BH_, 8), 256>>>();
    attn_out_kernel<<<dim3(BH_, N_ / 64), 256>>>();

    gemm2_cp<<<dim3(DIM_ / 128, MROWS / 128), 256>>>(Wout, bout, out);
}

// round 8
// speedup vs baseline: 1.8469x; 1.0840x over previous
#include <cuda_runtime.h>
#include <math.h>
#include <stdint.h>

#define B_   4
#define N_   8192
#define DIM_ 512
#define H_   8
#define DH_  64
#define BH_  (B_*H_)          // 32
#define MROWS (B_*N_)         // 32768
#define QKVN  (3*DIM_)        // 1536

typedef unsigned long long u64;

// ---------------- scratch (device globals; no allocs allowed) ----------------
__device__ float g_q[BH_*N_*DH_];      // [bh][n][d]
__device__ float g_k[BH_*N_*DH_];
__device__ float g_v[BH_*N_*DH_];
__device__ float g_attn[(size_t)MROWS*DIM_];  // [m][h*64+e]
__device__ float g_ctx[BH_*DH_*DH_];   // [bh][d][e]
__device__ float g_ksum[BH_*DH_];      // [bh][d]
__device__ int   g_maskflags[2];

// ---------------- helpers ----------------
__device__ __forceinline__ uint32_t smem_u32(const void* p) {
    uint32_t a;
    asm("{ .reg .u64 t; cvta.to.shared.u64 t, %1; cvt.u32.u64 %0, t; }" : "=r"(a) : "l"(p));
    return a;
}
__device__ __forceinline__ void cp16(uint32_t dst, const void* src) {
    asm volatile("cp.async.ca.shared.global [%0], [%1], 16;" :: "r"(dst), "l"(src));
}
__device__ __forceinline__ void cp_commit() {
    asm volatile("cp.async.commit_group;" ::: "memory");
}
template<int N> __device__ __forceinline__ void cp_wait() {
    asm volatile("cp.async.wait_group %0;" :: "n"(N) : "memory");
}

// packed f32x2 helpers (FFMA2 — B300 double-rate fp32)
__device__ __forceinline__ u64 pack_dup(float a) {
    u64 p;
    asm("mov.b64 %0, {%1, %1};" : "=l"(p) : "f"(a));
    return p;
}
__device__ __forceinline__ void fma2(u64& d, u64 a, u64 b) {
    asm("fma.rn.f32x2 %0, %1, %2, %0;" : "+l"(d) : "l"(a), "l"(b));
}
__device__ __forceinline__ void unpack2(float& lo, float& hi, u64 p) {
    asm("mov.b64 {%0, %1}, %2;" : "=f"(lo), "=f"(hi) : "l"(p));
}

// smem geometry: A stage = 128 rows x (16 floats + 4 pad) = 128*80 = 10240 B
//                B stage = 16 rows x (128 floats + 4 pad)  = 16*528 =  8448 B
#define A_STAGE 10240
#define B_BASE  20480
#define B_STAGE 8448
#define SMEM_TOT 37376

// =============================================================================
// cp.async double-buffered fp32 mainloop, packed f32x2 accumulation.
// C[128,128] over K=512 (32 stages of 16); 256 threads (16x16), 8x8 per thread.
// acc[i][jp] = packed pair (n0+2jp, n0+2jp+1) for row m0+i.
// =============================================================================
__device__ __forceinline__ void gemm_mainloop(u64 (&acc)[8][4], char* sm, uint32_t sb,
                                              const float* __restrict__ Ag,
                                              const float* __restrict__ Bg, int NW) {
    const int tid = threadIdx.x;
    const int ty = tid >> 4, tx = tid & 15;
    const int m0 = ty * 8;

    #pragma unroll
    for (int i = 0; i < 8; ++i)
        #pragma unroll
        for (int j = 0; j < 4; ++j) acc[i][j] = 0ull;   // two +0.0f

    const int ar_ = tid >> 2,  ac_ = tid & 3;
    const int br_ = tid >> 5,  bc_ = tid & 31;

    auto issue = [&](int ch, int p) {
        uint32_t Ab = sb + p * A_STAGE;
        uint32_t Bb = sb + B_BASE + p * B_STAGE;
        #pragma unroll
        for (int i = 0; i < 2; ++i) {
            int r = ar_ + i * 64;
            cp16(Ab + r * 80 + ac_ * 16,
                 Ag + (size_t)r * DIM_ + ch * 16 + ac_ * 4);
        }
        #pragma unroll
        for (int i = 0; i < 2; ++i) {
            int r = br_ + i * 8;
            cp16(Bb + r * 528 + bc_ * 16,
                 Bg + (size_t)(ch * 16 + r) * NW + bc_ * 4);
        }
    };

    issue(0, 0);
    cp_commit();

    #pragma unroll 1
    for (int ch = 0; ch < 32; ++ch) {
        int p = ch & 1;
        if (ch < 31) {
            issue(ch + 1, p ^ 1);
            cp_commit();
            cp_wait<1>();
        } else {
            cp_wait<0>();
        }
        __syncthreads();

        const float* As = (const float*)(sm + p * A_STAGE);
        const char*  Bs = sm + B_BASE + p * B_STAGE;

        #pragma unroll
        for (int kk = 0; kk < 16; ++kk) {
            const char* brow = Bs + kk * 528 + tx * 32;
            u64 b0 = *(const u64*)(brow);
            u64 b1 = *(const u64*)(brow + 8);
            u64 b2 = *(const u64*)(brow + 16);
            u64 b3 = *(const u64*)(brow + 24);
            #pragma unroll
            for (int i = 0; i < 8; ++i) {
                u64 pa = pack_dup(As[(m0 + i) * 20 + kk]);
                fma2(acc[i][0], pa, b0);
                fma2(acc[i][1], pa, b1);
                fma2(acc[i][2], pa, b2);
                fma2(acc[i][3], pa, b3);
            }
        }
        __syncthreads();
    }
}

// GEMM1: qkv = X @ Wqkv -> scatter into g_q/g_k/g_v
__global__ __launch_bounds__(256, 2) void gemm1_cp(const float* __restrict__ X,
                                                   const float* __restrict__ W) {
    __shared__ __align__(16) char sm[SMEM_TOT];
    uint32_t sb = smem_u32(sm);

    const int nBase = blockIdx.x * 128;
    const int mBase = blockIdx.y * 128;

    u64 accp[8][4];
    gemm_mainloop(accp, sm, sb, X + (size_t)mBase * DIM_, W + nBase, QKVN);

    float acc[8][8];
    #pragma unroll
    for (int i = 0; i < 8; ++i)
        #pragma unroll
        for (int j = 0; j < 4; ++j)
            unpack2(acc[i][2*j], acc[i][2*j+1], accp[i][j]);

    const int tid = threadIdx.x;
    const int ty = tid >> 4, tx = tid & 15;
    const int m0 = ty * 8, n0 = tx * 8;

    const int part    = nBase >> 9;
    const int rembase = nBase & 511;
    float* dstbuf = (part == 0) ? g_q : ((part == 1) ? g_k : g_v);

    #pragma unroll
    for (int i = 0; i < 8; ++i) {
        int gm = mBase + m0 + i;
        int b  = gm >> 13;
        int n  = gm & (N_ - 1);
        #pragma unroll
        for (int j = 0; j < 8; ++j) {
            int rem = rembase + n0 + j;
            int h = rem >> 6, d = rem & 63;
            dstbuf[(size_t)(((b << 3) + h) * N_ + n) * DH_ + d] = acc[i][j];
        }
    }
}

// GEMM2: out = g_attn @ Wout + bout
__global__ __launch_bounds__(256, 2) void gemm2_cp(const float* __restrict__ W,
                                                   const float* __restrict__ bias,
                                                   float* __restrict__ out) {
    __shared__ __align__(16) char sm[SMEM_TOT];
    uint32_t sb = smem_u32(sm);

    const int nBase = blockIdx.x * 128;
    const int mBase = blockIdx.y * 128;

    u64 accp[8][4];
    gemm_mainloop(accp, sm, sb, g_attn + (size_t)mBase * DIM_, W + nBase, DIM_);

    float acc[8][8];
    #pragma unroll
    for (int i = 0; i < 8; ++i)
        #pragma unroll
        for (int j = 0; j < 4; ++j)
            unpack2(acc[i][2*j], acc[i][2*j+1], accp[i][j]);

    const int tid = threadIdx.x;
    const int ty = tid >> 4, tx = tid & 15;
    const int m0 = ty * 8, n0 = tx * 8;

    #pragma unroll
    for (int i = 0; i < 8; ++i) {
        int gm = mBase + m0 + i;
        #pragma unroll
        for (int j = 0; j < 8; j += 4) {
            int gn = nBase + n0 + j;
            float4 bv = *(const float4*)&bias[gn];
            float4 o = make_float4(acc[i][j] + bv.x, acc[i][j+1] + bv.y,
                                   acc[i][j+2] + bv.z, acc[i][j+3] + bv.w);
            *(float4*)&out[(size_t)gm * DIM_ + gn] = o;
        }
    }
}

// =============================================================================
// q softmax over feature dim d=64 (after *SCALE). One warp per row.
// =============================================================================
__global__ __launch_bounds__(256) void qsoftmax_kernel() {
    const float SCALE = 0.125f;
    int gwarp = (blockIdx.x * 256 + threadIdx.x) >> 5;
    int lane  = threadIdx.x & 31;
    float2 v = *(const float2*)&g_q[(size_t)gwarp * 64 + lane * 2];
    float a = v.x * SCALE, b = v.y * SCALE;
    float mx = fmaxf(a, b);
    #pragma unroll
    for (int off = 16; off > 0; off >>= 1)
        mx = fmaxf(mx, __shfl_xor_sync(0xffffffff, mx, off));
    float ea = __expf(a - mx), eb = __expf(b - mx);
    float s = ea + eb;
    #pragma unroll
    for (int off = 16; off > 0; off >>= 1)
        s += __shfl_xor_sync(0xffffffff, s, off);
    float inv = 1.f / s;
    *(float2*)&g_q[(size_t)gwarp * 64 + lane * 2] = make_float2(ea * inv, eb * inv);
}

// =============================================================================
// k softmax over n: pass 1 — partial sums of exp(k) per (bh,d).
// =============================================================================
__global__ __launch_bounds__(256) void ksum_kernel() {
    int bh = blockIdx.x, chunk = blockIdx.y;
    int t = threadIdx.x;
    int d = t & 63, g = t >> 6;
    const float* kp = g_k + (size_t)bh * N_ * DH_;
    int nb = chunk * 1024 + g * 256;
    float s = 0.f;
    #pragma unroll 8
    for (int i = 0; i < 256; ++i)
        s += __expf(kp[(size_t)(nb + i) * DH_ + d]);
    __shared__ float red[4][64];
    red[g][d] = s;
    __syncthreads();
    if (g == 0)
        atomicAdd(&g_ksum[bh * DH_ + d], red[0][d] + red[1][d] + red[2][d] + red[3][d]);
}

// =============================================================================
// Mask dtype detection (bool may be serialized as u8 / i32 / f32).
// =============================================================================
__global__ __launch_bounds__(256) void detect_mask_kernel(const unsigned char* __restrict__ m) {
    int i = blockIdx.x * 256 + threadIdx.x;
    uchar4 v = ((const uchar4*)m)[i];
    bool f32sig = (v.w == 0x3f);
    bool offnz  = (v.y | v.z | v.w) != 0;
    unsigned b1 = __ballot_sync(0xffffffff, f32sig);
    unsigned b2 = __ballot_sync(0xffffffff, offnz);
    if ((threadIdx.x & 31) == 0) {
        if (b1) atomicOr(&g_maskflags[0], 1);
        if (b2) atomicOr(&g_maskflags[1], 1);
    }
}

// =============================================================================
// k softmax pass 2: k = mask ? 0 : exp(k)/sum.
// =============================================================================
__global__ __launch_bounds__(256) void knorm_kernel(const void* __restrict__ mask) {
    int i4  = blockIdx.x * 256 + threadIdx.x;
    int idx = i4 << 2;
    int row = idx >> 6;
    int d   = idx & 63;
    int bh  = row >> 13;

    int f32f = g_maskflags[0], u8f = g_maskflags[1];
    bool mz;
    if (f32f)      mz = ((const float*)mask)[row] != 0.f;
    else if (u8f)  mz = ((const unsigned char*)mask)[row] != 0;
    else           mz = ((const int*)mask)[row] != 0;

    float4 kv = *(const float4*)&g_k[idx];
    float4 o;
    if (mz) {
        o = make_float4(0.f, 0.f, 0.f, 0.f);
    } else {
        float4 sv = *(const float4*)&g_ksum[(bh << 6) + d];
        o.x = __expf(kv.x) / sv.x;
        o.y = __expf(kv.y) / sv.y;
        o.z = __expf(kv.z) / sv.z;
        o.w = __expf(kv.w) / sv.w;
    }
    *(float4*)&g_k[idx] = o;
}

// =============================================================================
// context[bh][d][e] += sum_n q[n,d]*k[n,e]
// =============================================================================
__global__ __launch_bounds__(256) void ctx_kernel() {
    int bh = blockIdx.x, chunk = blockIdx.y;
    __shared__ float qs[32][64];
    __shared__ float ks[32][64];
    int t = threadIdx.x;
    int d0 = (t >> 4) << 2, e0 = (t & 15) << 2;
    int lr = t >> 3, lc = (t & 7) << 3;

    const float* qp = g_q + (size_t)(bh * N_ + chunk * 1024) * DH_;
    const float* kp = g_k + (size_t)(bh * N_ + chunk * 1024) * DH_;

    float acc[4][4];
    #pragma unroll
    for (int i = 0; i < 4; ++i)
        #pragma unroll
        for (int j = 0; j < 4; ++j) acc[i][j] = 0.f;

    for (int it = 0; it < 32; ++it) {
        size_t base = (size_t)it * 32 * 64 + (size_t)lr * 64 + lc;
        *(float4*)&qs[lr][lc]   = *(const float4*)&qp[base];
        *(float4*)&qs[lr][lc+4] = *(const float4*)&qp[base + 4];
        *(float4*)&ks[lr][lc]   = *(const float4*)&kp[base];
        *(float4*)&ks[lr][lc+4] = *(const float4*)&kp[base + 4];
        __syncthreads();
        #pragma unroll
        for (int n = 0; n < 32; ++n) {
            float4 qa = *(float4*)&qs[n][d0];
            float4 ka = *(float4*)&ks[n][e0];
            float qr[4] = {qa.x,qa.y,qa.z,qa.w};
            float kr[4] = {ka.x,ka.y,ka.z,ka.w};
            #pragma unroll
            for (int i = 0; i < 4; ++i)
                #pragma unroll
                for (int j = 0; j < 4; ++j)
                    acc[i][j] += qr[i] * kr[j];
        }
        __syncthreads();
    }
    #pragma unroll
    for (int i = 0; i < 4; ++i)
        #pragma unroll
        for (int j = 0; j < 4; ++j)
            atomicAdd(&g_ctx[bh * 4096 + (d0 + i) * 64 + (e0 + j)], acc[i][j]);
}

// =============================================================================
// attn[m][h*64+e] = sum_d v[n,d]*ctx[d,e] (fp32)
// =============================================================================
__global__ __launch_bounds__(256) void attn_out_kernel() {
    int bh = blockIdx.x, chunk = blockIdx.y;
    __shared__ float cs[64][64];
    __shared__ float vs[64][64];
    int t = threadIdx.x;

    const float* cp = g_ctx + bh * 4096;
    const float* vp = g_v + (size_t)(bh * N_ + chunk * 64) * DH_;
    #pragma unroll
    for (int u = 0; u < 4; ++u) {
        ((float4*)cs)[u * 256 + t] = ((const float4*)cp)[u * 256 + t];
        ((float4*)vs)[u * 256 + t] = ((const float4*)vp)[u * 256 + t];
    }
    __syncthreads();

    int r64 = t >> 2;
    int e1 = (t & 3) << 4;
    float acc[16];
    #pragma unroll
    for (int j = 0; j < 16; ++j) acc[j] = 0.f;

    #pragma unroll
    for (int dd = 0; dd < 64; ++dd) {
        float vv = vs[r64][dd];
        #pragma unroll
        for (int j = 0; j < 16; ++j)
            acc[j] += vv * cs[dd][e1 + j];
    }

    int b = bh >> 3, h = bh & 7;
    size_t m = (size_t)b * N_ + chunk * 64 + r64;
    float* fdst = g_attn + m * DIM_ + h * 64 + e1;
    #pragma unroll
    for (int u = 0; u < 4; ++u)
        *(float4*)(fdst + u * 4) = make_float4(acc[u*4+0], acc[u*4+1], acc[u*4+2], acc[u*4+3]);
}

// =============================================================================
extern "C" void kernel_launch(void* const* d_in, const int* in_sizes, int n_in,
                              void* d_out, int out_size) {
    const float* x    = (const float*)d_in[0];
    const void*  mask = d_in[1];
    const float* Wqkv = (const float*)d_in[2];
    const float* Wout = (const float*)d_in[3];
    const float* bout = (const float*)d_in[4];
    float* out = (float*)d_out;

    void *pks, *pctx, *pfl;
    cudaGetSymbolAddress(&pks,  g_ksum);
    cudaGetSymbolAddress(&pctx, g_ctx);
    cudaGetSymbolAddress(&pfl,  g_maskflags);
    cudaMemsetAsync(pks,  0, sizeof(float) * BH_ * DH_);
    cudaMemsetAsync(pctx, 0, sizeof(float) * BH_ * DH_ * DH_);
    cudaMemsetAsync(pfl,  0, 2 * sizeof(int));

    gemm1_cp<<<dim3(QKVN / 128, MROWS / 128), 256>>>(x, Wqkv);

    qsoftmax_kernel<<<(BH_ * N_) / 8, 256>>>();
    ksum_kernel<<<dim3(BH_, 8), 256>>>();
    detect_mask_kernel<<<(BH_ * N_) / 1024, 256>>>((const unsigned char*)mask);
    knorm_kernel<<<(BH_ * N_ * DH_) / 1024, 256>>>(mask);
    ctx_kernel<<<dim3(BH_, 8), 256>>>();
    attn_out_kernel<<<dim3(BH_, N_ / 64), 256>>>();

    gemm2_cp<<<dim3(DIM_ / 128, MROWS / 128), 256>>>(Wout, bout, out);
}

// round 9
// speedup vs baseline: 1.8897x; 1.0232x over previous
#include <cuda_runtime.h>
#include <math.h>
#include <stdint.h>

#define B_   4
#define N_   8192
#define DIM_ 512
#define H_   8
#define DH_  64
#define BH_  (B_*H_)          // 32
#define MROWS (B_*N_)         // 32768
#define QKVN  (3*DIM_)        // 1536

typedef unsigned long long u64;

// ---------------- scratch (device globals; no allocs allowed) ----------------
__device__ float g_q[BH_*N_*DH_];      // [bh][n][d] (raw qkv output; softmax applied in ctx)
__device__ float g_k[BH_*N_*DH_];      // raw; normalized on the fly in ctx
__device__ float g_v[BH_*N_*DH_];
__device__ float g_attn[(size_t)MROWS*DIM_];  // [m][h*64+e]
__device__ float g_ctx[BH_*DH_*DH_];   // [bh][d][e]
__device__ float g_ksum[BH_*DH_];      // [bh][d]
__device__ int   g_maskflags[2];

// ---------------- helpers ----------------
__device__ __forceinline__ uint32_t smem_u32(const void* p) {
    uint32_t a;
    asm("{ .reg .u64 t; cvta.to.shared.u64 t, %1; cvt.u32.u64 %0, t; }" : "=r"(a) : "l"(p));
    return a;
}
__device__ __forceinline__ void cp16(uint32_t dst, const void* src) {
    asm volatile("cp.async.ca.shared.global [%0], [%1], 16;" :: "r"(dst), "l"(src));
}
__device__ __forceinline__ void cp_commit() {
    asm volatile("cp.async.commit_group;" ::: "memory");
}
template<int N> __device__ __forceinline__ void cp_wait() {
    asm volatile("cp.async.wait_group %0;" :: "n"(N) : "memory");
}

// packed f32x2 helpers (FFMA2)
__device__ __forceinline__ u64 pack_dup(float a) {
    u64 p;
    asm("mov.b64 %0, {%1, %1};" : "=l"(p) : "f"(a));
    return p;
}
__device__ __forceinline__ void fma2(u64& d, u64 a, u64 b) {
    asm("fma.rn.f32x2 %0, %1, %2, %0;" : "+l"(d) : "l"(a), "l"(b));
}
__device__ __forceinline__ void unpack2(float& lo, float& hi, u64 p) {
    asm("mov.b64 {%0, %1}, %2;" : "=f"(lo), "=f"(hi) : "l"(p));
}

// smem geometry: A stage = 128 rows x (16 floats + 4 pad) = 10240 B
//                B stage = 16 rows x (128 floats + 4 pad) = 8448 B
#define A_STAGE 10240
#define B_BASE  20480
#define B_STAGE 8448
#define SMEM_TOT 37376

// =============================================================================
// cp.async double-buffered fp32 mainloop, packed f32x2, ONE sync per chunk.
// C[128,128] over K=512 (32 stages of 16); 256 threads (16x16), 8x8 per thread.
// =============================================================================
__device__ __forceinline__ void gemm_mainloop(u64 (&acc)[8][4], char* sm, uint32_t sb,
                                              const float* __restrict__ Ag,
                                              const float* __restrict__ Bg, int NW) {
    const int tid = threadIdx.x;
    const int ty = tid >> 4, tx = tid & 15;
    const int m0 = ty * 8;

    #pragma unroll
    for (int i = 0; i < 8; ++i)
        #pragma unroll
        for (int j = 0; j < 4; ++j) acc[i][j] = 0ull;

    const int ar_ = tid >> 2,  ac_ = tid & 3;
    const int br_ = tid >> 5,  bc_ = tid & 31;

    auto issue = [&](int ch, int p) {
        uint32_t Ab = sb + p * A_STAGE;
        uint32_t Bb = sb + B_BASE + p * B_STAGE;
        #pragma unroll
        for (int i = 0; i < 2; ++i) {
            int r = ar_ + i * 64;
            cp16(Ab + r * 80 + ac_ * 16,
                 Ag + (size_t)r * DIM_ + ch * 16 + ac_ * 4);
        }
        #pragma unroll
        for (int i = 0; i < 2; ++i) {
            int r = br_ + i * 8;
            cp16(Bb + r * 528 + bc_ * 16,
                 Bg + (size_t)(ch * 16 + r) * NW + bc_ * 4);
        }
    };

    issue(0, 0);
    cp_commit();

    #pragma unroll 1
    for (int ch = 0; ch < 32; ++ch) {
        int p = ch & 1;
        cp_wait<0>();          // only stage ch in flight here
        __syncthreads();       // data visible to all; prior compute on p^1 done
        if (ch < 31) {
            issue(ch + 1, p ^ 1);   // overlaps with compute below
            cp_commit();
        }

        const float* As = (const float*)(sm + p * A_STAGE);
        const char*  Bs = sm + B_BASE + p * B_STAGE;

        #pragma unroll
        for (int kk = 0; kk < 16; ++kk) {
            const char* brow = Bs + kk * 528 + tx * 32;
            u64 b0 = *(const u64*)(brow);
            u64 b1 = *(const u64*)(brow + 8);
            u64 b2 = *(const u64*)(brow + 16);
            u64 b3 = *(const u64*)(brow + 24);
            #pragma unroll
            for (int i = 0; i < 8; ++i) {
                u64 pa = pack_dup(As[(m0 + i) * 20 + kk]);
                fma2(acc[i][0], pa, b0);
                fma2(acc[i][1], pa, b1);
                fma2(acc[i][2], pa, b2);
                fma2(acc[i][3], pa, b3);
            }
        }
    }
}

// GEMM1: qkv = X @ Wqkv -> scatter into g_q/g_k/g_v
__global__ __launch_bounds__(256, 2) void gemm1_cp(const float* __restrict__ X,
                                                   const float* __restrict__ W) {
    __shared__ __align__(16) char sm[SMEM_TOT];
    uint32_t sb = smem_u32(sm);

    const int nBase = blockIdx.x * 128;
    const int mBase = blockIdx.y * 128;

    u64 accp[8][4];
    gemm_mainloop(accp, sm, sb, X + (size_t)mBase * DIM_, W + nBase, QKVN);

    float acc[8][8];
    #pragma unroll
    for (int i = 0; i < 8; ++i)
        #pragma unroll
        for (int j = 0; j < 4; ++j)
            unpack2(acc[i][2*j], acc[i][2*j+1], accp[i][j]);

    const int tid = threadIdx.x;
    const int ty = tid >> 4, tx = tid & 15;
    const int m0 = ty * 8, n0 = tx * 8;

    const int part    = nBase >> 9;
    const int rembase = nBase & 511;
    float* dstbuf = (part == 0) ? g_q : ((part == 1) ? g_k : g_v);

    #pragma unroll
    for (int i = 0; i < 8; ++i) {
        int gm = mBase + m0 + i;
        int b  = gm >> 13;
        int n  = gm & (N_ - 1);
        #pragma unroll
        for (int j = 0; j < 8; ++j) {
            int rem = rembase + n0 + j;
            int h = rem >> 6, d = rem & 63;
            dstbuf[(size_t)(((b << 3) + h) * N_ + n) * DH_ + d] = acc[i][j];
        }
    }
}

// GEMM2: out = g_attn @ Wout + bout
__global__ __launch_bounds__(256, 2) void gemm2_cp(const float* __restrict__ W,
                                                   const float* __restrict__ bias,
                                                   float* __restrict__ out) {
    __shared__ __align__(16) char sm[SMEM_TOT];
    uint32_t sb = smem_u32(sm);

    const int nBase = blockIdx.x * 128;
    const int mBase = blockIdx.y * 128;

    u64 accp[8][4];
    gemm_mainloop(accp, sm, sb, g_attn + (size_t)mBase * DIM_, W + nBase, DIM_);

    float acc[8][8];
    #pragma unroll
    for (int i = 0; i < 8; ++i)
        #pragma unroll
        for (int j = 0; j < 4; ++j)
            unpack2(acc[i][2*j], acc[i][2*j+1], accp[i][j]);

    const int tid = threadIdx.x;
    const int ty = tid >> 4, tx = tid & 15;
    const int m0 = ty * 8, n0 = tx * 8;

    #pragma unroll
    for (int i = 0; i < 8; ++i) {
        int gm = mBase + m0 + i;
        #pragma unroll
        for (int j = 0; j < 8; j += 4) {
            int gn = nBase + n0 + j;
            float4 bv = *(const float4*)&bias[gn];
            float4 o = make_float4(acc[i][j] + bv.x, acc[i][j+1] + bv.y,
                                   acc[i][j+2] + bv.z, acc[i][j+3] + bv.w);
            *(float4*)&out[(size_t)gm * DIM_ + gn] = o;
        }
    }
}

// =============================================================================
// k softmax pass 1 — partial sums of exp(k) per (bh,d).
// =============================================================================
__global__ __launch_bounds__(256) void ksum_kernel() {
    int bh = blockIdx.x, chunk = blockIdx.y;
    int t = threadIdx.x;
    int d = t & 63, g = t >> 6;
    const float* kp = g_k + (size_t)bh * N_ * DH_;
    int nb = chunk * 1024 + g * 256;
    float s = 0.f;
    #pragma unroll 8
    for (int i = 0; i < 256; ++i)
        s += __expf(kp[(size_t)(nb + i) * DH_ + d]);
    __shared__ float red[4][64];
    red[g][d] = s;
    __syncthreads();
    if (g == 0)
        atomicAdd(&g_ksum[bh * DH_ + d], red[0][d] + red[1][d] + red[2][d] + red[3][d]);
}

// =============================================================================
// Mask dtype detection (bool may be serialized as u8 / i32 / f32).
// =============================================================================
__global__ __launch_bounds__(256) void detect_mask_kernel(const unsigned char* __restrict__ m) {
    int i = blockIdx.x * 256 + threadIdx.x;
    uchar4 v = ((const uchar4*)m)[i];
    bool f32sig = (v.w == 0x3f);
    bool offnz  = (v.y | v.z | v.w) != 0;
    unsigned b1 = __ballot_sync(0xffffffff, f32sig);
    unsigned b2 = __ballot_sync(0xffffffff, offnz);
    if ((threadIdx.x & 31) == 0) {
        if (b1) atomicOr(&g_maskflags[0], 1);
        if (b2) atomicOr(&g_maskflags[1], 1);
    }
}

// =============================================================================
// FUSED ctx: applies q-softmax (over d) and k-normalize (exp/ksum, mask) on
// tile load, then accumulates context[bh][d][e] += sum_n q[n,d]*k[n,e].
// grid (32 bh, 16 chunks of 512 rows). 256 threads.
// =============================================================================
#define CTX_CHUNK 512
#define CTX_TILES (CTX_CHUNK / 32)

__global__ __launch_bounds__(256) void ctx_fused_kernel(const void* __restrict__ mask) {
    int bh = blockIdx.x, chunk = blockIdx.y;
    __shared__ float qs[32][64];
    __shared__ float ks[32][64];
    int t = threadIdx.x;
    int d0 = (t >> 4) << 2, e0 = (t & 15) << 2;
    int lr = t >> 3, lc = (t & 7) << 3;
    const float SCALE = 0.125f;

    const int f32f = g_maskflags[0], u8f = g_maskflags[1];

    const float* qp = g_q + (size_t)(bh * N_ + chunk * CTX_CHUNK) * DH_;
    const float* kp = g_k + (size_t)(bh * N_ + chunk * CTX_CHUNK) * DH_;

    float sv8[8];
    #pragma unroll
    for (int j = 0; j < 8; ++j) sv8[j] = g_ksum[bh * DH_ + lc + j];

    float acc[4][4];
    #pragma unroll
    for (int i = 0; i < 4; ++i)
        #pragma unroll
        for (int j = 0; j < 4; ++j) acc[i][j] = 0.f;

    for (int it = 0; it < CTX_TILES; ++it) {
        size_t base = (size_t)it * 32 * 64 + (size_t)lr * 64 + lc;
        float4 qa0 = *(const float4*)&qp[base];
        float4 qa1 = *(const float4*)&qp[base + 4];
        float4 ka0 = *(const float4*)&kp[base];
        float4 ka1 = *(const float4*)&kp[base + 4];
        float q8[8] = {qa0.x, qa0.y, qa0.z, qa0.w, qa1.x, qa1.y, qa1.z, qa1.w};
        float k8[8] = {ka0.x, ka0.y, ka0.z, ka0.w, ka1.x, ka1.y, ka1.z, ka1.w};

        // q softmax over d=64: row lr spans the 8 lanes of this lane-group
        float mx = q8[0] * SCALE;
        #pragma unroll
        for (int j = 0; j < 8; ++j) { q8[j] *= SCALE; mx = fmaxf(mx, q8[j]); }
        #pragma unroll
        for (int off = 4; off > 0; off >>= 1)
            mx = fmaxf(mx, __shfl_xor_sync(0xffffffff, mx, off));
        float s = 0.f;
        #pragma unroll
        for (int j = 0; j < 8; ++j) { q8[j] = __expf(q8[j] - mx); s += q8[j]; }
        #pragma unroll
        for (int off = 4; off > 0; off >>= 1)
            s += __shfl_xor_sync(0xffffffff, s, off);
        float inv = 1.f / s;

        // k mask + normalize (same math as old knorm: __expf(kv)/sv)
        int grow = bh * N_ + chunk * CTX_CHUNK + it * 32 + lr;
        bool mz;
        if (f32f)      mz = ((const float*)mask)[grow] != 0.f;
        else if (u8f)  mz = ((const unsigned char*)mask)[grow] != 0;
        else           mz = ((const int*)mask)[grow] != 0;

        if (it) __syncthreads();     // previous FMA phase done before overwrite
        #pragma unroll
        for (int j = 0; j < 8; ++j) {
            qs[lr][lc + j] = q8[j] * inv;
            ks[lr][lc + j] = mz ? 0.f : (__expf(k8[j]) / sv8[j]);
        }
        __syncthreads();

        #pragma unroll
        for (int n = 0; n < 32; ++n) {
            float4 qa = *(float4*)&qs[n][d0];
            float4 ka = *(float4*)&ks[n][e0];
            float qr[4] = {qa.x, qa.y, qa.z, qa.w};
            float kr[4] = {ka.x, ka.y, ka.z, ka.w};
            #pragma unroll
            for (int i = 0; i < 4; ++i)
                #pragma unroll
                for (int j = 0; j < 4; ++j)
                    acc[i][j] += qr[i] * kr[j];
        }
    }
    #pragma unroll
    for (int i = 0; i < 4; ++i)
        #pragma unroll
        for (int j = 0; j < 4; ++j)
            atomicAdd(&g_ctx[bh * 4096 + (d0 + i) * 64 + (e0 + j)], acc[i][j]);
}

// =============================================================================
// attn[m][h*64+e] = sum_d v[n,d]*ctx[d,e] (fp32)
// =============================================================================
__global__ __launch_bounds__(256) void attn_out_kernel() {
    int bh = blockIdx.x, chunk = blockIdx.y;
    __shared__ float cs[64][64];
    __shared__ float vs[64][64];
    int t = threadIdx.x;

    const float* cp = g_ctx + bh * 4096;
    const float* vp = g_v + (size_t)(bh * N_ + chunk * 64) * DH_;
    #pragma unroll
    for (int u = 0; u < 4; ++u) {
        ((float4*)cs)[u * 256 + t] = ((const float4*)cp)[u * 256 + t];
        ((float4*)vs)[u * 256 + t] = ((const float4*)vp)[u * 256 + t];
    }
    __syncthreads();

    int r64 = t >> 2;
    int e1 = (t & 3) << 4;
    float acc[16];
    #pragma unroll
    for (int j = 0; j < 16; ++j) acc[j] = 0.f;

    #pragma unroll
    for (int dd = 0; dd < 64; ++dd) {
        float vv = vs[r64][dd];
        #pragma unroll
        for (int j = 0; j < 16; ++j)
            acc[j] += vv * cs[dd][e1 + j];
    }

    int b = bh >> 3, h = bh & 7;
    size_t m = (size_t)b * N_ + chunk * 64 + r64;
    float* fdst = g_attn + m * DIM_ + h * 64 + e1;
    #pragma unroll
    for (int u = 0; u < 4; ++u)
        *(float4*)(fdst + u * 4) = make_float4(acc[u*4+0], acc[u*4+1], acc[u*4+2], acc[u*4+3]);
}

// =============================================================================
extern "C" void kernel_launch(void* const* d_in, const int* in_sizes, int n_in,
                              void* d_out, int out_size) {
    const float* x    = (const float*)d_in[0];
    const void*  mask = d_in[1];
    const float* Wqkv = (const float*)d_in[2];
    const float* Wout = (const float*)d_in[3];
    const float* bout = (const float*)d_in[4];
    float* out = (float*)d_out;

    void *pks, *pctx, *pfl;
    cudaGetSymbolAddress(&pks,  g_ksum);
    cudaGetSymbolAddress(&pctx, g_ctx);
    cudaGetSymbolAddress(&pfl,  g_maskflags);
    cudaMemsetAsync(pks,  0, sizeof(float) * BH_ * DH_);
    cudaMemsetAsync(pctx, 0, sizeof(float) * BH_ * DH_ * DH_);
    cudaMemsetAsync(pfl,  0, 2 * sizeof(int));

    gemm1_cp<<<dim3(QKVN / 128, MROWS / 128), 256>>>(x, Wqkv);

    ksum_kernel<<<dim3(BH_, 8), 256>>>();
    detect_mask_kernel<<<(BH_ * N_) / 1024, 256>>>((const unsigned char*)mask);
    ctx_fused_kernel<<<dim3(BH_, N_ / CTX_CHUNK), 256>>>(mask);
    attn_out_kernel<<<dim3(BH_, N_ / 64), 256>>>();

    gemm2_cp<<<dim3(DIM_ / 128, MROWS / 128), 256>>>(Wout, bout, out);
}

// round 10
// speedup vs baseline: 2.2180x; 1.1737x over previous
#include <cuda_runtime.h>
#include <math.h>
#include <stdint.h>

#define B_   4
#define N_   8192
#define DIM_ 512
#define H_   8
#define DH_  64
#define BH_  (B_*H_)          // 32
#define MROWS (B_*N_)         // 32768
#define QKVN  (3*DIM_)        // 1536

typedef unsigned long long u64;

// ---------------- scratch (device globals; no allocs allowed) ----------------
__device__ float g_q[BH_*N_*DH_];      // raw q; softmax applied in ctx
__device__ float g_k[BH_*N_*DH_];      // raw k; normalized on the fly in ctx
__device__ float g_v[BH_*N_*DH_];
__device__ float g_ctx[BH_*DH_*DH_];   // [bh][d][e]
__device__ float g_w2[(size_t)B_*DIM_*DIM_];   // [b][h*64+d][c] = ctx_h @ Wout_h
__device__ float g_ksum[BH_*DH_];      // [bh][d]
__device__ int   g_maskflags[2];

// ---------------- helpers ----------------
__device__ __forceinline__ uint32_t smem_u32(const void* p) {
    uint32_t a;
    asm("{ .reg .u64 t; cvta.to.shared.u64 t, %1; cvt.u32.u64 %0, t; }" : "=r"(a) : "l"(p));
    return a;
}
__device__ __forceinline__ void cp16(uint32_t dst, const void* src) {
    asm volatile("cp.async.ca.shared.global [%0], [%1], 16;" :: "r"(dst), "l"(src));
}
__device__ __forceinline__ void cp_commit() {
    asm volatile("cp.async.commit_group;" ::: "memory");
}
template<int N> __device__ __forceinline__ void cp_wait() {
    asm volatile("cp.async.wait_group %0;" :: "n"(N) : "memory");
}

// packed f32x2 helpers (FFMA2)
__device__ __forceinline__ u64 pack_dup(float a) {
    u64 p;
    asm("mov.b64 %0, {%1, %1};" : "=l"(p) : "f"(a));
    return p;
}
__device__ __forceinline__ void fma2(u64& d, u64 a, u64 b) {
    asm("fma.rn.f32x2 %0, %1, %2, %0;" : "+l"(d) : "l"(a), "l"(b));
}
__device__ __forceinline__ void unpack2(float& lo, float& hi, u64 p) {
    asm("mov.b64 {%0, %1}, %2;" : "=f"(lo), "=f"(hi) : "l"(p));
}

// smem geometry: A stage = 128 rows x (16 floats + 4 pad) = 10240 B
//                B stage = 16 rows x (128 floats + 4 pad) = 8448 B
#define A_STAGE 10240
#define B_BASE  20480
#define B_STAGE 8448
#define SMEM_TOT 37376

// =============================================================================
// GEMM1: qkv = X @ Wqkv -> scatter into g_q/g_k/g_v; k-part tiles also
// accumulate exp-sums into g_ksum (fused ksum).
// =============================================================================
__global__ __launch_bounds__(256, 2) void gemm1_cp(const float* __restrict__ X,
                                                   const float* __restrict__ W) {
    __shared__ __align__(16) char sm[SMEM_TOT];
    uint32_t sb = smem_u32(sm);

    const int nBase = blockIdx.x * 128;
    const int mBase = blockIdx.y * 128;
    const float* Ag = X + (size_t)mBase * DIM_;
    const float* Bg = W + nBase;

    const int tid = threadIdx.x;
    const int ty = tid >> 4, tx = tid & 15;
    const int m0 = ty * 8;

    u64 accp[8][4];
    #pragma unroll
    for (int i = 0; i < 8; ++i)
        #pragma unroll
        for (int j = 0; j < 4; ++j) accp[i][j] = 0ull;

    const int ar_ = tid >> 2,  ac_ = tid & 3;
    const int br_ = tid >> 5,  bc_ = tid & 31;

    auto issue = [&](int ch, int p) {
        uint32_t Ab = sb + p * A_STAGE;
        uint32_t Bb = sb + B_BASE + p * B_STAGE;
        #pragma unroll
        for (int i = 0; i < 2; ++i) {
            int r = ar_ + i * 64;
            cp16(Ab + r * 80 + ac_ * 16, Ag + (size_t)r * DIM_ + ch * 16 + ac_ * 4);
        }
        #pragma unroll
        for (int i = 0; i < 2; ++i) {
            int r = br_ + i * 8;
            cp16(Bb + r * 528 + bc_ * 16, Bg + (size_t)(ch * 16 + r) * QKVN + bc_ * 4);
        }
    };

    issue(0, 0);
    cp_commit();

    #pragma unroll 1
    for (int ch = 0; ch < 32; ++ch) {
        int p = ch & 1;
        cp_wait<0>();
        __syncthreads();
        if (ch < 31) { issue(ch + 1, p ^ 1); cp_commit(); }

        const float* As = (const float*)(sm + p * A_STAGE);
        const char*  Bs = sm + B_BASE + p * B_STAGE;

        #pragma unroll
        for (int kk = 0; kk < 16; ++kk) {
            const char* brow = Bs + kk * 528 + tx * 32;
            u64 b0 = *(const u64*)(brow);
            u64 b1 = *(const u64*)(brow + 8);
            u64 b2 = *(const u64*)(brow + 16);
            u64 b3 = *(const u64*)(brow + 24);
            #pragma unroll
            for (int i = 0; i < 8; ++i) {
                u64 pa = pack_dup(As[(m0 + i) * 20 + kk]);
                fma2(accp[i][0], pa, b0);
                fma2(accp[i][1], pa, b1);
                fma2(accp[i][2], pa, b2);
                fma2(accp[i][3], pa, b3);
            }
        }
    }

    float acc[8][8];
    #pragma unroll
    for (int i = 0; i < 8; ++i)
        #pragma unroll
        for (int j = 0; j < 4; ++j)
            unpack2(acc[i][2*j], acc[i][2*j+1], accp[i][j]);

    const int n0 = tx * 8;
    const int part    = nBase >> 9;
    const int rembase = nBase & 511;
    const int b       = mBase >> 13;
    float* dstbuf = (part == 0) ? g_q : ((part == 1) ? g_k : g_v);

    #pragma unroll
    for (int i = 0; i < 8; ++i) {
        int gm = mBase + m0 + i;
        int n  = gm & (N_ - 1);
        #pragma unroll
        for (int j = 0; j < 8; ++j) {
            int rem = rembase + n0 + j;
            int h = rem >> 6, d = rem & 63;
            dstbuf[(size_t)(((b << 3) + h) * N_ + n) * DH_ + d] = acc[i][j];
        }
    }

    // fused ksum: k-part tiles accumulate exp-sums per output column
    if (part == 1) {
        __syncthreads();                 // mainloop smem no longer needed
        float* red = (float*)sm;         // 16 x 128 floats = 8 KB
        #pragma unroll
        for (int j = 0; j < 8; ++j) {
            float s = 0.f;
            #pragma unroll
            for (int i = 0; i < 8; ++i) s += __expf(acc[i][j]);
            red[ty * 128 + n0 + j] = s;
        }
        __syncthreads();
        if (tid < 128) {
            float s = 0.f;
            #pragma unroll
            for (int r = 0; r < 16; ++r) s += red[r * 128 + tid];
            int rem = rembase + tid;
            int h = rem >> 6, d = rem & 63;
            atomicAdd(&g_ksum[((b << 3) + h) * DH_ + d], s);
        }
    }
}

// =============================================================================
// GEMM2: out = v' @ W2 + bout, where A'[m][h*64+d] = v[b,h,n,d] gathered
// on the fly and W2[b] = ctx_h @ Wout_h (precomputed). Same FLOPs as attn@Wout.
// =============================================================================
__global__ __launch_bounds__(256, 2) void gemm2_cp(const float* __restrict__ bias,
                                                   float* __restrict__ out) {
    __shared__ __align__(16) char sm[SMEM_TOT];
    uint32_t sb = smem_u32(sm);

    const int nBase = blockIdx.x * 128;
    const int mBase = blockIdx.y * 128;
    const int b     = mBase >> 13;
    const int nb    = mBase & (N_ - 1);
    const float* Vg = g_v + (size_t)(b << 3) * N_ * DH_;   // + h*N*64 per chunk
    const float* Bg = g_w2 + (size_t)b * DIM_ * DIM_ + nBase;

    const int tid = threadIdx.x;
    const int ty = tid >> 4, tx = tid & 15;
    const int m0 = ty * 8;

    u64 accp[8][4];
    #pragma unroll
    for (int i = 0; i < 8; ++i)
        #pragma unroll
        for (int j = 0; j < 4; ++j) accp[i][j] = 0ull;

    const int ar_ = tid >> 2,  ac_ = tid & 3;
    const int br_ = tid >> 5,  bc_ = tid & 31;

    auto issue = [&](int ch, int p) {
        uint32_t Ab = sb + p * A_STAGE;
        uint32_t Bb = sb + B_BASE + p * B_STAGE;
        int k0 = ch * 16 + ac_ * 4;
        int h  = k0 >> 6, d0 = k0 & 63;
        const float* vh = Vg + (size_t)h * N_ * DH_ + (size_t)nb * DH_ + d0;
        #pragma unroll
        for (int i = 0; i < 2; ++i) {
            int r = ar_ + i * 64;
            cp16(Ab + r * 80 + ac_ * 16, vh + (size_t)r * DH_);
        }
        #pragma unroll
        for (int i = 0; i < 2; ++i) {
            int r = br_ + i * 8;
            cp16(Bb + r * 528 + bc_ * 16, Bg + (size_t)(ch * 16 + r) * DIM_ + bc_ * 4);
        }
    };

    issue(0, 0);
    cp_commit();

    #pragma unroll 1
    for (int ch = 0; ch < 32; ++ch) {
        int p = ch & 1;
        cp_wait<0>();
        __syncthreads();
        if (ch < 31) { issue(ch + 1, p ^ 1); cp_commit(); }

        const float* As = (const float*)(sm + p * A_STAGE);
        const char*  Bs = sm + B_BASE + p * B_STAGE;

        #pragma unroll
        for (int kk = 0; kk < 16; ++kk) {
            const char* brow = Bs + kk * 528 + tx * 32;
            u64 b0 = *(const u64*)(brow);
            u64 b1 = *(const u64*)(brow + 8);
            u64 b2 = *(const u64*)(brow + 16);
            u64 b3 = *(const u64*)(brow + 24);
            #pragma unroll
            for (int i = 0; i < 8; ++i) {
                u64 pa = pack_dup(As[(m0 + i) * 20 + kk]);
                fma2(accp[i][0], pa, b0);
                fma2(accp[i][1], pa, b1);
                fma2(accp[i][2], pa, b2);
                fma2(accp[i][3], pa, b3);
            }
        }
    }

    float acc[8][8];
    #pragma unroll
    for (int i = 0; i < 8; ++i)
        #pragma unroll
        for (int j = 0; j < 4; ++j)
            unpack2(acc[i][2*j], acc[i][2*j+1], accp[i][j]);

    const int n0 = tx * 8;
    #pragma unroll
    for (int i = 0; i < 8; ++i) {
        int gm = mBase + m0 + i;
        #pragma unroll
        for (int j = 0; j < 8; j += 4) {
            int gn = nBase + n0 + j;
            float4 bv = *(const float4*)&bias[gn];
            float4 o = make_float4(acc[i][j] + bv.x, acc[i][j+1] + bv.y,
                                   acc[i][j+2] + bv.z, acc[i][j+3] + bv.w);
            *(float4*)&out[(size_t)gm * DIM_ + gn] = o;
        }
    }
}

// =============================================================================
// Mask dtype detection (bool may be serialized as u8 / i32 / f32).
// =============================================================================
__global__ __launch_bounds__(256) void detect_mask_kernel(const unsigned char* __restrict__ m) {
    int i = blockIdx.x * 256 + threadIdx.x;
    uchar4 v = ((const uchar4*)m)[i];
    bool f32sig = (v.w == 0x3f);
    bool offnz  = (v.y | v.z | v.w) != 0;
    unsigned b1 = __ballot_sync(0xffffffff, f32sig);
    unsigned b2 = __ballot_sync(0xffffffff, offnz);
    if ((threadIdx.x & 31) == 0) {
        if (b1) atomicOr(&g_maskflags[0], 1);
        if (b2) atomicOr(&g_maskflags[1], 1);
    }
}

// =============================================================================
// FUSED ctx: q-softmax + k-normalize on tile load, f32x2 accumulation.
// grid (32 bh, 32 chunks of 256 rows). 256 threads.
// =============================================================================
#define CTX_CHUNK 256
#define CTX_TILES (CTX_CHUNK / 32)

__global__ __launch_bounds__(256) void ctx_fused_kernel(const void* __restrict__ mask) {
    int bh = blockIdx.x, chunk = blockIdx.y;
    __shared__ float qs[32][64];
    __shared__ float ks[32][64];
    int t = threadIdx.x;
    int d0 = (t >> 4) << 2, e0 = (t & 15) << 2;
    int lr = t >> 3, lc = (t & 7) << 3;
    const float SCALE = 0.125f;

    const int f32f = g_maskflags[0], u8f = g_maskflags[1];

    const float* qp = g_q + (size_t)(bh * N_ + chunk * CTX_CHUNK) * DH_;
    const float* kp = g_k + (size_t)(bh * N_ + chunk * CTX_CHUNK) * DH_;

    float sv8[8];
    #pragma unroll
    for (int j = 0; j < 8; ++j) sv8[j] = g_ksum[bh * DH_ + lc + j];

    u64 accp[4][2];
    #pragma unroll
    for (int i = 0; i < 4; ++i) { accp[i][0] = 0ull; accp[i][1] = 0ull; }

    for (int it = 0; it < CTX_TILES; ++it) {
        size_t base = (size_t)it * 32 * 64 + (size_t)lr * 64 + lc;
        float4 qa0 = *(const float4*)&qp[base];
        float4 qa1 = *(const float4*)&qp[base + 4];
        float4 ka0 = *(const float4*)&kp[base];
        float4 ka1 = *(const float4*)&kp[base + 4];
        float q8[8] = {qa0.x, qa0.y, qa0.z, qa0.w, qa1.x, qa1.y, qa1.z, qa1.w};
        float k8[8] = {ka0.x, ka0.y, ka0.z, ka0.w, ka1.x, ka1.y, ka1.z, ka1.w};

        // q softmax over d=64 (8 lanes per row group)
        float mx = q8[0] * SCALE;
        #pragma unroll
        for (int j = 0; j < 8; ++j) { q8[j] *= SCALE; mx = fmaxf(mx, q8[j]); }
        #pragma unroll
        for (int off = 4; off > 0; off >>= 1)
            mx = fmaxf(mx, __shfl_xor_sync(0xffffffff, mx, off));
        float s = 0.f;
        #pragma unroll
        for (int j = 0; j < 8; ++j) { q8[j] = __expf(q8[j] - mx); s += q8[j]; }
        #pragma unroll
        for (int off = 4; off > 0; off >>= 1)
            s += __shfl_xor_sync(0xffffffff, s, off);
        float inv = 1.f / s;

        int grow = bh * N_ + chunk * CTX_CHUNK + it * 32 + lr;
        bool mz;
        if (f32f)      mz = ((const float*)mask)[grow] != 0.f;
        else if (u8f)  mz = ((const unsigned char*)mask)[grow] != 0;
        else           mz = ((const int*)mask)[grow] != 0;

        if (it) __syncthreads();
        #pragma unroll
        for (int j = 0; j < 8; ++j) {
            qs[lr][lc + j] = q8[j] * inv;
            ks[lr][lc + j] = mz ? 0.f : (__expf(k8[j]) / sv8[j]);
        }
        __syncthreads();

        #pragma unroll
        for (int n = 0; n < 32; ++n) {
            float4 qa = *(float4*)&qs[n][d0];
            u64 kb0 = *(const u64*)&ks[n][e0];
            u64 kb1 = *(const u64*)&ks[n][e0 + 2];
            u64 p0 = pack_dup(qa.x), p1 = pack_dup(qa.y);
            u64 p2 = pack_dup(qa.z), p3 = pack_dup(qa.w);
            fma2(accp[0][0], p0, kb0); fma2(accp[0][1], p0, kb1);
            fma2(accp[1][0], p1, kb0); fma2(accp[1][1], p1, kb1);
            fma2(accp[2][0], p2, kb0); fma2(accp[2][1], p2, kb1);
            fma2(accp[3][0], p3, kb0); fma2(accp[3][1], p3, kb1);
        }
    }
    #pragma unroll
    for (int i = 0; i < 4; ++i) {
        float v0, v1, v2, v3;
        unpack2(v0, v1, accp[i][0]);
        unpack2(v2, v3, accp[i][1]);
        float* dst = &g_ctx[bh * 4096 + (d0 + i) * 64 + e0];
        atomicAdd(dst + 0, v0);
        atomicAdd(dst + 1, v1);
        atomicAdd(dst + 2, v2);
        atomicAdd(dst + 3, v3);
    }
}

// =============================================================================
// W2[b][h*64+d][c] = sum_e ctx[bh][d][e] * Wout[h*64+e][c]
// grid (32 bh, 4 c-blocks of 128). 256 threads; each thread 4 d x 8 c.
// =============================================================================
__global__ __launch_bounds__(256) void w2_kernel(const float* __restrict__ Wout) {
    int bh = blockIdx.x, cb = blockIdx.y;
    int b = bh >> 3, h = bh & 7;
    __shared__ float cs[64][64];
    int t = threadIdx.x;

    const float* cp = g_ctx + bh * 4096;
    #pragma unroll
    for (int u = 0; u < 4; ++u)
        ((float4*)cs)[u * 256 + t] = ((const float4*)cp)[u * 256 + t];
    __syncthreads();

    int ty = t >> 4, tx = t & 15;
    int c0 = cb * 128 + tx * 8;
    float acc[4][8];
    #pragma unroll
    for (int i = 0; i < 4; ++i)
        #pragma unroll
        for (int j = 0; j < 8; ++j) acc[i][j] = 0.f;

    for (int e = 0; e < 64; ++e) {
        const float* wr = Wout + (size_t)(h * 64 + e) * DIM_ + c0;
        float4 w0 = *(const float4*)wr;
        float4 w1 = *(const float4*)(wr + 4);
        float wv[8] = {w0.x, w0.y, w0.z, w0.w, w1.x, w1.y, w1.z, w1.w};
        #pragma unroll
        for (int i = 0; i < 4; ++i) {
            float cv = cs[ty * 4 + i][e];
            #pragma unroll
            for (int j = 0; j < 8; ++j) acc[i][j] += cv * wv[j];
        }
    }

    #pragma unroll
    for (int i = 0; i < 4; ++i) {
        size_t row = (size_t)b * DIM_ + h * 64 + ty * 4 + i;
        float* dst = g_w2 + row * DIM_ + c0;
        *(float4*)(dst)     = make_float4(acc[i][0], acc[i][1], acc[i][2], acc[i][3]);
        *(float4*)(dst + 4) = make_float4(acc[i][4], acc[i][5], acc[i][6], acc[i][7]);
    }
}

// =============================================================================
extern "C" void kernel_launch(void* const* d_in, const int* in_sizes, int n_in,
                              void* d_out, int out_size) {
    const float* x    = (const float*)d_in[0];
    const void*  mask = d_in[1];
    const float* Wqkv = (const float*)d_in[2];
    const float* Wout = (const float*)d_in[3];
    const float* bout = (const float*)d_in[4];
    float* out = (float*)d_out;

    void *pks, *pctx, *pfl;
    cudaGetSymbolAddress(&pks,  g_ksum);
    cudaGetSymbolAddress(&pctx, g_ctx);
    cudaGetSymbolAddress(&pfl,  g_maskflags);
    cudaMemsetAsync(pks,  0, sizeof(float) * BH_ * DH_);
    cudaMemsetAsync(pctx, 0, sizeof(float) * BH_ * DH_ * DH_);
    cudaMemsetAsync(pfl,  0, 2 * sizeof(int));

    gemm1_cp<<<dim3(QKVN / 128, MROWS / 128), 256>>>(x, Wqkv);   // incl. fused ksum

    detect_mask_kernel<<<(BH_ * N_) / 1024, 256>>>((const unsigned char*)mask);
    ctx_fused_kernel<<<dim3(BH_, N_ / CTX_CHUNK), 256>>>(mask);
    w2_kernel<<<dim3(BH_, 4), 256>>>(Wout);

    gemm2_cp<<<dim3(DIM_ / 128, MROWS / 128), 256>>>(bout, out);
}

// round 11
// speedup vs baseline: 2.5649x; 1.1564x over previous
#include <cuda_runtime.h>
#include <math.h>
#include <stdint.h>

#define B_   4
#define N_   8192
#define DIM_ 512
#define H_   8
#define DH_  64
#define BH_  (B_*H_)          // 32
#define MROWS (B_*N_)         // 32768
#define QKVN  (3*DIM_)        // 1536
#define QKN   (2*DIM_)        // 1024 (q+k columns only)

typedef unsigned long long u64;

// ---------------- scratch (device globals; no allocs allowed) ----------------
__device__ float g_q[BH_*N_*DH_];      // raw q; softmax applied in ctx
__device__ float g_k[BH_*N_*DH_];      // raw k; normalized on the fly in ctx
__device__ float g_ctx[BH_*DH_*DH_];   // [bh][d][e]
__device__ float g_w2[(size_t)B_*DIM_*DIM_];   // [b][h*64+d][c] = ctx_h @ Wout_h
__device__ float g_w3[(size_t)B_*DIM_*DIM_];   // [b][k][c]      = Wv @ W2[b]
__device__ float g_ksum[BH_*DH_];      // [bh][d]
__device__ int   g_maskflags[2];

// ---------------- helpers ----------------
__device__ __forceinline__ uint32_t smem_u32(const void* p) {
    uint32_t a;
    asm("{ .reg .u64 t; cvta.to.shared.u64 t, %1; cvt.u32.u64 %0, t; }" : "=r"(a) : "l"(p));
    return a;
}
__device__ __forceinline__ void cp16(uint32_t dst, const void* src) {
    asm volatile("cp.async.ca.shared.global [%0], [%1], 16;" :: "r"(dst), "l"(src));
}
__device__ __forceinline__ void cp_commit() {
    asm volatile("cp.async.commit_group;" ::: "memory");
}
template<int N> __device__ __forceinline__ void cp_wait() {
    asm volatile("cp.async.wait_group %0;" :: "n"(N) : "memory");
}

// packed f32x2 helpers (FFMA2)
__device__ __forceinline__ u64 pack_dup(float a) {
    u64 p;
    asm("mov.b64 %0, {%1, %1};" : "=l"(p) : "f"(a));
    return p;
}
__device__ __forceinline__ void fma2(u64& d, u64 a, u64 b) {
    asm("fma.rn.f32x2 %0, %1, %2, %0;" : "+l"(d) : "l"(a), "l"(b));
}
__device__ __forceinline__ void unpack2(float& lo, float& hi, u64 p) {
    asm("mov.b64 {%0, %1}, %2;" : "=f"(lo), "=f"(hi) : "l"(p));
}

// smem geometry: A stage = 128 rows x (16 floats + 4 pad) = 10240 B
//                B stage = 16 rows x (128 floats + 4 pad) = 8448 B
#define A_STAGE 10240
#define B_BASE  20480
#define B_STAGE 8448
#define SMEM_TOT 37376

// =============================================================================
// Shared cp.async double-buffered f32x2 mainloop: C[128,128] over K=512.
// A row stride AW, B row stride BW (elements). 256 threads (16x16), 8x8/thread.
// =============================================================================
__device__ __forceinline__ void gemm_mainloop(u64 (&accp)[8][4], char* sm, uint32_t sb,
                                              const float* __restrict__ Ag, int AW,
                                              const float* __restrict__ Bg, int BW) {
    const int tid = threadIdx.x;
    const int ty = tid >> 4, tx = tid & 15;
    const int m0 = ty * 8;

    #pragma unroll
    for (int i = 0; i < 8; ++i)
        #pragma unroll
        for (int j = 0; j < 4; ++j) accp[i][j] = 0ull;

    const int ar_ = tid >> 2,  ac_ = tid & 3;
    const int br_ = tid >> 5,  bc_ = tid & 31;

    auto issue = [&](int ch, int p) {
        uint32_t Ab = sb + p * A_STAGE;
        uint32_t Bb = sb + B_BASE + p * B_STAGE;
        #pragma unroll
        for (int i = 0; i < 2; ++i) {
            int r = ar_ + i * 64;
            cp16(Ab + r * 80 + ac_ * 16, Ag + (size_t)r * AW + ch * 16 + ac_ * 4);
        }
        #pragma unroll
        for (int i = 0; i < 2; ++i) {
            int r = br_ + i * 8;
            cp16(Bb + r * 528 + bc_ * 16, Bg + (size_t)(ch * 16 + r) * BW + bc_ * 4);
        }
    };

    issue(0, 0);
    cp_commit();

    #pragma unroll 1
    for (int ch = 0; ch < 32; ++ch) {
        int p = ch & 1;
        cp_wait<0>();
        __syncthreads();
        if (ch < 31) { issue(ch + 1, p ^ 1); cp_commit(); }

        const float* As = (const float*)(sm + p * A_STAGE);
        const char*  Bs = sm + B_BASE + p * B_STAGE;

        #pragma unroll
        for (int kk = 0; kk < 16; ++kk) {
            const char* brow = Bs + kk * 528 + tx * 32;
            u64 b0 = *(const u64*)(brow);
            u64 b1 = *(const u64*)(brow + 8);
            u64 b2 = *(const u64*)(brow + 16);
            u64 b3 = *(const u64*)(brow + 24);
            #pragma unroll
            for (int i = 0; i < 8; ++i) {
                u64 pa = pack_dup(As[(m0 + i) * 20 + kk]);
                fma2(accp[i][0], pa, b0);
                fma2(accp[i][1], pa, b1);
                fma2(accp[i][2], pa, b2);
                fma2(accp[i][3], pa, b3);
            }
        }
    }
}

// =============================================================================
// GEMM1: [q|k] = X @ Wqkv[:, 0:1024] -> scatter into g_q/g_k; k-part tiles
// also accumulate exp-sums into g_ksum (fused ksum). grid (8, 256).
// =============================================================================
__global__ __launch_bounds__(256, 2) void gemm1_cp(const float* __restrict__ X,
                                                   const float* __restrict__ W) {
    __shared__ __align__(16) char sm[SMEM_TOT];
    uint32_t sb = smem_u32(sm);

    const int nBase = blockIdx.x * 128;
    const int mBase = blockIdx.y * 128;

    u64 accp[8][4];
    gemm_mainloop(accp, sm, sb, X + (size_t)mBase * DIM_, DIM_, W + nBase, QKVN);

    float acc[8][8];
    #pragma unroll
    for (int i = 0; i < 8; ++i)
        #pragma unroll
        for (int j = 0; j < 4; ++j)
            unpack2(acc[i][2*j], acc[i][2*j+1], accp[i][j]);

    const int tid = threadIdx.x;
    const int ty = tid >> 4, tx = tid & 15;
    const int m0 = ty * 8, n0 = tx * 8;
    const int part    = nBase >> 9;            // 0 = q, 1 = k
    const int rembase = nBase & 511;
    const int b       = mBase >> 13;
    float* dstbuf = part ? g_k : g_q;

    #pragma unroll
    for (int i = 0; i < 8; ++i) {
        int gm = mBase + m0 + i;
        int n  = gm & (N_ - 1);
        #pragma unroll
        for (int j = 0; j < 8; ++j) {
            int rem = rembase + n0 + j;
            int h = rem >> 6, d = rem & 63;
            dstbuf[(size_t)(((b << 3) + h) * N_ + n) * DH_ + d] = acc[i][j];
        }
    }

    if (part == 1) {
        __syncthreads();
        float* red = (float*)sm;         // 16 x 128 floats
        #pragma unroll
        for (int j = 0; j < 8; ++j) {
            float s = 0.f;
            #pragma unroll
            for (int i = 0; i < 8; ++i) s += __expf(acc[i][j]);
            red[ty * 128 + n0 + j] = s;
        }
        __syncthreads();
        if (tid < 128) {
            float s = 0.f;
            #pragma unroll
            for (int r = 0; r < 16; ++r) s += red[r * 128 + tid];
            int rem = rembase + tid;
            int h = rem >> 6, d = rem & 63;
            atomicAdd(&g_ksum[((b << 3) + h) * DH_ + d], s);
        }
    }
}

// =============================================================================
// W3[b] = Wv @ W2[b]  (Wv = Wqkv columns [1024:1536]).  grid (4, 16): 64 CTAs.
// =============================================================================
__global__ __launch_bounds__(256, 2) void w3_kernel(const float* __restrict__ Wqkv) {
    __shared__ __align__(16) char sm[SMEM_TOT];
    uint32_t sb = smem_u32(sm);

    const int nBase = blockIdx.x * 128;
    const int mBase = blockIdx.y * 128;          // over 4*512 rows
    const int b     = mBase >> 9;
    const int kr0   = mBase & 511;

    u64 accp[8][4];
    gemm_mainloop(accp, sm, sb,
                  Wqkv + (size_t)kr0 * QKVN + 1024, QKVN,
                  g_w2 + (size_t)b * DIM_ * DIM_ + nBase, DIM_);

    float acc[8][8];
    #pragma unroll
    for (int i = 0; i < 8; ++i)
        #pragma unroll
        for (int j = 0; j < 4; ++j)
            unpack2(acc[i][2*j], acc[i][2*j+1], accp[i][j]);

    const int tid = threadIdx.x;
    const int ty = tid >> 4, tx = tid & 15;
    const int m0 = ty * 8, n0 = tx * 8;

    #pragma unroll
    for (int i = 0; i < 8; ++i) {
        float* dst = g_w3 + (size_t)b * DIM_ * DIM_ + (size_t)(kr0 + m0 + i) * DIM_ + nBase + n0;
        #pragma unroll
        for (int j = 0; j < 8; j += 4)
            *(float4*)(dst + j) = make_float4(acc[i][j], acc[i][j+1], acc[i][j+2], acc[i][j+3]);
    }
}

// =============================================================================
// GEMM2: out = X @ W3[b] + bout.  grid (4, 256).
// =============================================================================
__global__ __launch_bounds__(256, 2) void gemm2_cp(const float* __restrict__ X,
                                                   const float* __restrict__ bias,
                                                   float* __restrict__ out) {
    __shared__ __align__(16) char sm[SMEM_TOT];
    uint32_t sb = smem_u32(sm);

    const int nBase = blockIdx.x * 128;
    const int mBase = blockIdx.y * 128;
    const int b     = mBase >> 13;

    u64 accp[8][4];
    gemm_mainloop(accp, sm, sb,
                  X + (size_t)mBase * DIM_, DIM_,
                  g_w3 + (size_t)b * DIM_ * DIM_ + nBase, DIM_);

    float acc[8][8];
    #pragma unroll
    for (int i = 0; i < 8; ++i)
        #pragma unroll
        for (int j = 0; j < 4; ++j)
            unpack2(acc[i][2*j], acc[i][2*j+1], accp[i][j]);

    const int tid = threadIdx.x;
    const int ty = tid >> 4, tx = tid & 15;
    const int m0 = ty * 8, n0 = tx * 8;

    #pragma unroll
    for (int i = 0; i < 8; ++i) {
        int gm = mBase + m0 + i;
        #pragma unroll
        for (int j = 0; j < 8; j += 4) {
            int gn = nBase + n0 + j;
            float4 bv = *(const float4*)&bias[gn];
            float4 o = make_float4(acc[i][j] + bv.x, acc[i][j+1] + bv.y,
                                   acc[i][j+2] + bv.z, acc[i][j+3] + bv.w);
            *(float4*)&out[(size_t)gm * DIM_ + gn] = o;
        }
    }
}

// =============================================================================
// Mask dtype detection (bool may be serialized as u8 / i32 / f32).
// =============================================================================
__global__ __launch_bounds__(256) void detect_mask_kernel(const unsigned char* __restrict__ m) {
    int i = blockIdx.x * 256 + threadIdx.x;
    uchar4 v = ((const uchar4*)m)[i];
    bool f32sig = (v.w == 0x3f);
    bool offnz  = (v.y | v.z | v.w) != 0;
    unsigned b1 = __ballot_sync(0xffffffff, f32sig);
    unsigned b2 = __ballot_sync(0xffffffff, offnz);
    if ((threadIdx.x & 31) == 0) {
        if (b1) atomicOr(&g_maskflags[0], 1);
        if (b2) atomicOr(&g_maskflags[1], 1);
    }
}

// =============================================================================
// FUSED ctx: q-softmax + k-normalize on tile load, f32x2 accumulation.
// grid (32 bh, 32 chunks of 256 rows). 256 threads.
// =============================================================================
#define CTX_CHUNK 256
#define CTX_TILES (CTX_CHUNK / 32)

__global__ __launch_bounds__(256) void ctx_fused_kernel(const void* __restrict__ mask) {
    int bh = blockIdx.x, chunk = blockIdx.y;
    __shared__ float qs[32][64];
    __shared__ float ks[32][64];
    int t = threadIdx.x;
    int d0 = (t >> 4) << 2, e0 = (t & 15) << 2;
    int lr = t >> 3, lc = (t & 7) << 3;
    const float SCALE = 0.125f;

    const int f32f = g_maskflags[0], u8f = g_maskflags[1];

    const float* qp = g_q + (size_t)(bh * N_ + chunk * CTX_CHUNK) * DH_;
    const float* kp = g_k + (size_t)(bh * N_ + chunk * CTX_CHUNK) * DH_;

    float sv8[8];
    #pragma unroll
    for (int j = 0; j < 8; ++j) sv8[j] = g_ksum[bh * DH_ + lc + j];

    u64 accp[4][2];
    #pragma unroll
    for (int i = 0; i < 4; ++i) { accp[i][0] = 0ull; accp[i][1] = 0ull; }

    for (int it = 0; it < CTX_TILES; ++it) {
        size_t base = (size_t)it * 32 * 64 + (size_t)lr * 64 + lc;
        float4 qa0 = *(const float4*)&qp[base];
        float4 qa1 = *(const float4*)&qp[base + 4];
        float4 ka0 = *(const float4*)&kp[base];
        float4 ka1 = *(const float4*)&kp[base + 4];
        float q8[8] = {qa0.x, qa0.y, qa0.z, qa0.w, qa1.x, qa1.y, qa1.z, qa1.w};
        float k8[8] = {ka0.x, ka0.y, ka0.z, ka0.w, ka1.x, ka1.y, ka1.z, ka1.w};

        float mx = q8[0] * SCALE;
        #pragma unroll
        for (int j = 0; j < 8; ++j) { q8[j] *= SCALE; mx = fmaxf(mx, q8[j]); }
        #pragma unroll
        for (int off = 4; off > 0; off >>= 1)
            mx = fmaxf(mx, __shfl_xor_sync(0xffffffff, mx, off));
        float s = 0.f;
        #pragma unroll
        for (int j = 0; j < 8; ++j) { q8[j] = __expf(q8[j] - mx); s += q8[j]; }
        #pragma unroll
        for (int off = 4; off > 0; off >>= 1)
            s += __shfl_xor_sync(0xffffffff, s, off);
        float inv = 1.f / s;

        int grow = bh * N_ + chunk * CTX_CHUNK + it * 32 + lr;
        bool mz;
        if (f32f)      mz = ((const float*)mask)[grow] != 0.f;
        else if (u8f)  mz = ((const unsigned char*)mask)[grow] != 0;
        else           mz = ((const int*)mask)[grow] != 0;

        if (it) __syncthreads();
        #pragma unroll
        for (int j = 0; j < 8; ++j) {
            qs[lr][lc + j] = q8[j] * inv;
            ks[lr][lc + j] = mz ? 0.f : (__expf(k8[j]) / sv8[j]);
        }
        __syncthreads();

        #pragma unroll
        for (int n = 0; n < 32; ++n) {
            float4 qa = *(float4*)&qs[n][d0];
            u64 kb0 = *(const u64*)&ks[n][e0];
            u64 kb1 = *(const u64*)&ks[n][e0 + 2];
            u64 p0 = pack_dup(qa.x), p1 = pack_dup(qa.y);
            u64 p2 = pack_dup(qa.z), p3 = pack_dup(qa.w);
            fma2(accp[0][0], p0, kb0); fma2(accp[0][1], p0, kb1);
            fma2(accp[1][0], p1, kb0); fma2(accp[1][1], p1, kb1);
            fma2(accp[2][0], p2, kb0); fma2(accp[2][1], p2, kb1);
            fma2(accp[3][0], p3, kb0); fma2(accp[3][1], p3, kb1);
        }
    }
    #pragma unroll
    for (int i = 0; i < 4; ++i) {
        float v0, v1, v2, v3;
        unpack2(v0, v1, accp[i][0]);
        unpack2(v2, v3, accp[i][1]);
        float* dst = &g_ctx[bh * 4096 + (d0 + i) * 64 + e0];
        atomicAdd(dst + 0, v0);
        atomicAdd(dst + 1, v1);
        atomicAdd(dst + 2, v2);
        atomicAdd(dst + 3, v3);
    }
}

// =============================================================================
// W2[b][h*64+d][c] = sum_e ctx[bh][d][e] * Wout[h*64+e][c]
// grid (32 bh, 4 c-blocks of 128). 256 threads; each thread 4 d x 8 c.
// =============================================================================
__global__ __launch_bounds__(256) void w2_kernel(const float* __restrict__ Wout) {
    int bh = blockIdx.x, cb = blockIdx.y;
    int b = bh >> 3, h = bh & 7;
    __shared__ float cs[64][64];
    int t = threadIdx.x;

    const float* cp = g_ctx + bh * 4096;
    #pragma unroll
    for (int u = 0; u < 4; ++u)
        ((float4*)cs)[u * 256 + t] = ((const float4*)cp)[u * 256 + t];
    __syncthreads();

    int ty = t >> 4, tx = t & 15;
    int c0 = cb * 128 + tx * 8;
    float acc[4][8];
    #pragma unroll
    for (int i = 0; i < 4; ++i)
        #pragma unroll
        for (int j = 0; j < 8; ++j) acc[i][j] = 0.f;

    for (int e = 0; e < 64; ++e) {
        const float* wr = Wout + (size_t)(h * 64 + e) * DIM_ + c0;
        float4 w0 = *(const float4*)wr;
        float4 w1 = *(const float4*)(wr + 4);
        float wv[8] = {w0.x, w0.y, w0.z, w0.w, w1.x, w1.y, w1.z, w1.w};
        #pragma unroll
        for (int i = 0; i < 4; ++i) {
            float cv = cs[ty * 4 + i][e];
            #pragma unroll
            for (int j = 0; j < 8; ++j) acc[i][j] += cv * wv[j];
        }
    }

    #pragma unroll
    for (int i = 0; i < 4; ++i) {
        size_t row = (size_t)b * DIM_ + h * 64 + ty * 4 + i;
        float* dst = g_w2 + row * DIM_ + c0;
        *(float4*)(dst)     = make_float4(acc[i][0], acc[i][1], acc[i][2], acc[i][3]);
        *(float4*)(dst + 4) = make_float4(acc[i][4], acc[i][5], acc[i][6], acc[i][7]);
    }
}

// =============================================================================
extern "C" void kernel_launch(void* const* d_in, const int* in_sizes, int n_in,
                              void* d_out, int out_size) {
    const float* x    = (const float*)d_in[0];
    const void*  mask = d_in[1];
    const float* Wqkv = (const float*)d_in[2];
    const float* Wout = (const float*)d_in[3];
    const float* bout = (const float*)d_in[4];
    float* out = (float*)d_out;

    void *pks, *pctx, *pfl;
    cudaGetSymbolAddress(&pks,  g_ksum);
    cudaGetSymbolAddress(&pctx, g_ctx);
    cudaGetSymbolAddress(&pfl,  g_maskflags);
    cudaMemsetAsync(pks,  0, sizeof(float) * BH_ * DH_);
    cudaMemsetAsync(pctx, 0, sizeof(float) * BH_ * DH_ * DH_);
    cudaMemsetAsync(pfl,  0, 2 * sizeof(int));

    gemm1_cp<<<dim3(QKN / 128, MROWS / 128), 256>>>(x, Wqkv);   // q,k only + fused ksum

    detect_mask_kernel<<<(BH_ * N_) / 1024, 256>>>((const unsigned char*)mask);
    ctx_fused_kernel<<<dim3(BH_, N_ / CTX_CHUNK), 256>>>(mask);
    w2_kernel<<<dim3(BH_, 4), 256>>>(Wout);
    w3_kernel<<<dim3(4, 16), 256>>>(Wqkv);

    gemm2_cp<<<dim3(DIM_ / 128, MROWS / 128), 256>>>(x, bout, out);
}

// round 12
// speedup vs baseline: 2.7513x; 1.0727x over previous
#include <cuda_runtime.h>
#include <math.h>
#include <stdint.h>

#define B_   4
#define N_   8192
#define DIM_ 512
#define H_   8
#define DH_  64
#define BH_  (B_*H_)          // 32
#define MROWS (B_*N_)         // 32768
#define QKVN  (3*DIM_)        // 1536
#define QKN   (2*DIM_)        // 1024 (q+k columns only)

typedef unsigned long long u64;

// ---------------- scratch (device globals; no allocs allowed) ----------------
__device__ float g_q[BH_*N_*DH_];      // raw q; softmax applied in ctx
__device__ float g_k[BH_*N_*DH_];      // raw k; exp/mask applied in ctx
__device__ float g_ctx[BH_*DH_*DH_];   // [bh][d][e]  UNNORMALIZED (divide in w2)
__device__ float g_w2[(size_t)B_*DIM_*DIM_];   // [b][h*64+d][c] = (ctx_h/ksum) @ Wout_h
__device__ float g_w3[(size_t)B_*DIM_*DIM_];   // [b][k][c]      = Wv @ W2[b]
__device__ float g_ksum[BH_*DH_];      // [bh][e] = sum_n exp(k)
__device__ int   g_maskflags[2];

// ---------------- helpers ----------------
__device__ __forceinline__ uint32_t smem_u32(const void* p) {
    uint32_t a;
    asm("{ .reg .u64 t; cvta.to.shared.u64 t, %1; cvt.u32.u64 %0, t; }" : "=r"(a) : "l"(p));
    return a;
}
__device__ __forceinline__ void cp16(uint32_t dst, const void* src) {
    asm volatile("cp.async.ca.shared.global [%0], [%1], 16;" :: "r"(dst), "l"(src));
}
__device__ __forceinline__ void cp_commit() {
    asm volatile("cp.async.commit_group;" ::: "memory");
}
template<int N> __device__ __forceinline__ void cp_wait() {
    asm volatile("cp.async.wait_group %0;" :: "n"(N) : "memory");
}

// packed f32x2 helpers (FFMA2)
__device__ __forceinline__ u64 pack_dup(float a) {
    u64 p;
    asm("mov.b64 %0, {%1, %1};" : "=l"(p) : "f"(a));
    return p;
}
__device__ __forceinline__ void fma2(u64& d, u64 a, u64 b) {
    asm("fma.rn.f32x2 %0, %1, %2, %0;" : "+l"(d) : "l"(a), "l"(b));
}
__device__ __forceinline__ void unpack2(float& lo, float& hi, u64 p) {
    asm("mov.b64 {%0, %1}, %2;" : "=f"(lo), "=f"(hi) : "l"(p));
}

// smem geometry: A stage = 128 rows x (16 floats + 4 pad) = 10240 B
//                B stage = 16 rows x (128 floats + 4 pad) = 8448 B
#define A_STAGE 10240
#define B_BASE  20480
#define B_STAGE 8448
#define SMEM_TOT 37376

// =============================================================================
// Shared cp.async double-buffered f32x2 mainloop: C[128,128] over nch*16 K.
// A row stride AW, B row stride BW. K chunks [ch0, ch0+nch).
// =============================================================================
__device__ __forceinline__ void gemm_mainloop(u64 (&accp)[8][4], char* sm, uint32_t sb,
                                              const float* __restrict__ Ag, int AW,
                                              const float* __restrict__ Bg, int BW,
                                              int ch0, int nch) {
    const int tid = threadIdx.x;
    const int ty = tid >> 4, tx = tid & 15;
    const int m0 = ty * 8;

    #pragma unroll
    for (int i = 0; i < 8; ++i)
        #pragma unroll
        for (int j = 0; j < 4; ++j) accp[i][j] = 0ull;

    const int ar_ = tid >> 2,  ac_ = tid & 3;
    const int br_ = tid >> 5,  bc_ = tid & 31;

    auto issue = [&](int ch, int p) {
        uint32_t Ab = sb + p * A_STAGE;
        uint32_t Bb = sb + B_BASE + p * B_STAGE;
        int kc = (ch0 + ch) * 16;
        #pragma unroll
        for (int i = 0; i < 2; ++i) {
            int r = ar_ + i * 64;
            cp16(Ab + r * 80 + ac_ * 16, Ag + (size_t)r * AW + kc + ac_ * 4);
        }
        #pragma unroll
        for (int i = 0; i < 2; ++i) {
            int r = br_ + i * 8;
            cp16(Bb + r * 528 + bc_ * 16, Bg + (size_t)(kc + r) * BW + bc_ * 4);
        }
    };

    issue(0, 0);
    cp_commit();

    #pragma unroll 1
    for (int ch = 0; ch < nch; ++ch) {
        int p = ch & 1;
        cp_wait<0>();
        __syncthreads();
        if (ch < nch - 1) { issue(ch + 1, p ^ 1); cp_commit(); }

        const float* As = (const float*)(sm + p * A_STAGE);
        const char*  Bs = sm + B_BASE + p * B_STAGE;

        #pragma unroll
        for (int kk = 0; kk < 16; ++kk) {
            const char* brow = Bs + kk * 528 + tx * 32;
            u64 b0 = *(const u64*)(brow);
            u64 b1 = *(const u64*)(brow + 8);
            u64 b2 = *(const u64*)(brow + 16);
            u64 b3 = *(const u64*)(brow + 24);
            #pragma unroll
            for (int i = 0; i < 8; ++i) {
                u64 pa = pack_dup(As[(m0 + i) * 20 + kk]);
                fma2(accp[i][0], pa, b0);
                fma2(accp[i][1], pa, b1);
                fma2(accp[i][2], pa, b2);
                fma2(accp[i][3], pa, b3);
            }
        }
    }
}

// =============================================================================
// GEMM1: [q|k] = X @ Wqkv[:, 0:1024] -> scatter into g_q/g_k. grid (8, 256).
// =============================================================================
__global__ __launch_bounds__(256, 2) void gemm1_cp(const float* __restrict__ X,
                                                   const float* __restrict__ W) {
    __shared__ __align__(16) char sm[SMEM_TOT];
    uint32_t sb = smem_u32(sm);

    const int nBase = blockIdx.x * 128;
    const int mBase = blockIdx.y * 128;

    u64 accp[8][4];
    gemm_mainloop(accp, sm, sb, X + (size_t)mBase * DIM_, DIM_, W + nBase, QKVN, 0, 32);

    float acc[8][8];
    #pragma unroll
    for (int i = 0; i < 8; ++i)
        #pragma unroll
        for (int j = 0; j < 4; ++j)
            unpack2(acc[i][2*j], acc[i][2*j+1], accp[i][j]);

    const int tid = threadIdx.x;
    const int ty = tid >> 4, tx = tid & 15;
    const int m0 = ty * 8, n0 = tx * 8;
    const int part    = nBase >> 9;            // 0 = q, 1 = k
    const int rembase = nBase & 511;
    const int b       = mBase >> 13;
    float* dstbuf = part ? g_k : g_q;

    #pragma unroll
    for (int i = 0; i < 8; ++i) {
        int gm = mBase + m0 + i;
        int n  = gm & (N_ - 1);
        #pragma unroll
        for (int j = 0; j < 8; ++j) {
            int rem = rembase + n0 + j;
            int h = rem >> 6, d = rem & 63;
            dstbuf[(size_t)(((b << 3) + h) * N_ + n) * DH_ + d] = acc[i][j];
        }
    }
}

// =============================================================================
// W3[b] += Wv_slice @ W2[b]  (K-split 4, atomicAdd). grid (4, 16, 4).
// =============================================================================
__global__ __launch_bounds__(256, 2) void w3_kernel(const float* __restrict__ Wqkv) {
    __shared__ __align__(16) char sm[SMEM_TOT];
    uint32_t sb = smem_u32(sm);

    const int nBase = blockIdx.x * 128;
    const int mBase = blockIdx.y * 128;          // over 4*512 rows
    const int b     = mBase >> 9;
    const int kr0   = mBase & 511;
    const int ks    = blockIdx.z;                // 0..3

    u64 accp[8][4];
    gemm_mainloop(accp, sm, sb,
                  Wqkv + (size_t)kr0 * QKVN + 1024, QKVN,
                  g_w2 + (size_t)b * DIM_ * DIM_ + nBase, DIM_,
                  ks * 8, 8);

    float acc[8][8];
    #pragma unroll
    for (int i = 0; i < 8; ++i)
        #pragma unroll
        for (int j = 0; j < 4; ++j)
            unpack2(acc[i][2*j], acc[i][2*j+1], accp[i][j]);

    const int tid = threadIdx.x;
    const int ty = tid >> 4, tx = tid & 15;
    const int m0 = ty * 8, n0 = tx * 8;

    #pragma unroll
    for (int i = 0; i < 8; ++i) {
        float* dst = g_w3 + (size_t)b * DIM_ * DIM_ + (size_t)(kr0 + m0 + i) * DIM_ + nBase + n0;
        #pragma unroll
        for (int j = 0; j < 8; ++j) atomicAdd(dst + j, acc[i][j]);
    }
}

// =============================================================================
// GEMM2: out = X @ W3[b] + bout.  grid (4, 256).
// =============================================================================
__global__ __launch_bounds__(256, 2) void gemm2_cp(const float* __restrict__ X,
                                                   const float* __restrict__ bias,
                                                   float* __restrict__ out) {
    __shared__ __align__(16) char sm[SMEM_TOT];
    uint32_t sb = smem_u32(sm);

    const int nBase = blockIdx.x * 128;
    const int mBase = blockIdx.y * 128;
    const int b     = mBase >> 13;

    u64 accp[8][4];
    gemm_mainloop(accp, sm, sb,
                  X + (size_t)mBase * DIM_, DIM_,
                  g_w3 + (size_t)b * DIM_ * DIM_ + nBase, DIM_, 0, 32);

    float acc[8][8];
    #pragma unroll
    for (int i = 0; i < 8; ++i)
        #pragma unroll
        for (int j = 0; j < 4; ++j)
            unpack2(acc[i][2*j], acc[i][2*j+1], accp[i][j]);

    const int tid = threadIdx.x;
    const int ty = tid >> 4, tx = tid & 15;
    const int m0 = ty * 8, n0 = tx * 8;

    #pragma unroll
    for (int i = 0; i < 8; ++i) {
        int gm = mBase + m0 + i;
        #pragma unroll
        for (int j = 0; j < 8; j += 4) {
            int gn = nBase + n0 + j;
            float4 bv = *(const float4*)&bias[gn];
            float4 o = make_float4(acc[i][j] + bv.x, acc[i][j+1] + bv.y,
                                   acc[i][j+2] + bv.z, acc[i][j+3] + bv.w);
            *(float4*)&out[(size_t)gm * DIM_ + gn] = o;
        }
    }
}

// =============================================================================
// Mask dtype detection (bool may be serialized as u8 / i32 / f32).
// =============================================================================
__global__ __launch_bounds__(256) void detect_mask_kernel(const unsigned char* __restrict__ m) {
    int i = blockIdx.x * 256 + threadIdx.x;
    uchar4 v = ((const uchar4*)m)[i];
    bool f32sig = (v.w == 0x3f);
    bool offnz  = (v.y | v.z | v.w) != 0;
    unsigned b1 = __ballot_sync(0xffffffff, f32sig);
    unsigned b2 = __ballot_sync(0xffffffff, offnz);
    if ((threadIdx.x & 31) == 0) {
        if (b1) atomicOr(&g_maskflags[0], 1);
        if (b2) atomicOr(&g_maskflags[1], 1);
    }
}

// =============================================================================
// FUSED ctx: q-softmax + k exp/mask (UNNORMALIZED) + local ksum reduction.
// ctxU[d][e] = sum_n q~[n,d] * (mask?0:exp(k[n,e])); ksum[e] += sum_n exp(k[n,e]).
// grid (32 bh, 32 chunks of 256 rows). 256 threads.
// =============================================================================
#define CTX_CHUNK 256
#define CTX_TILES (CTX_CHUNK / 32)

__global__ __launch_bounds__(256) void ctx_fused_kernel(const void* __restrict__ mask) {
    int bh = blockIdx.x, chunk = blockIdx.y;
    __shared__ float qs[32][64];
    __shared__ float ks[32][64];
    int t = threadIdx.x;
    int d0 = (t >> 4) << 2, e0 = (t & 15) << 2;
    int lr = t >> 3, lc = (t & 7) << 3;
    const float SCALE = 0.125f;

    const int f32f = g_maskflags[0], u8f = g_maskflags[1];

    const float* qp = g_q + (size_t)(bh * N_ + chunk * CTX_CHUNK) * DH_;
    const float* kp = g_k + (size_t)(bh * N_ + chunk * CTX_CHUNK) * DH_;

    float ksl[8];
    #pragma unroll
    for (int j = 0; j < 8; ++j) ksl[j] = 0.f;

    u64 accp[4][2];
    #pragma unroll
    for (int i = 0; i < 4; ++i) { accp[i][0] = 0ull; accp[i][1] = 0ull; }

    for (int it = 0; it < CTX_TILES; ++it) {
        size_t base = (size_t)it * 32 * 64 + (size_t)lr * 64 + lc;
        float4 qa0 = *(const float4*)&qp[base];
        float4 qa1 = *(const float4*)&qp[base + 4];
        float4 ka0 = *(const float4*)&kp[base];
        float4 ka1 = *(const float4*)&kp[base + 4];
        float q8[8] = {qa0.x, qa0.y, qa0.z, qa0.w, qa1.x, qa1.y, qa1.z, qa1.w};
        float k8[8] = {ka0.x, ka0.y, ka0.z, ka0.w, ka1.x, ka1.y, ka1.z, ka1.w};

        // q softmax over d=64 (8 lanes per row group)
        float mx = q8[0] * SCALE;
        #pragma unroll
        for (int j = 0; j < 8; ++j) { q8[j] *= SCALE; mx = fmaxf(mx, q8[j]); }
        #pragma unroll
        for (int off = 4; off > 0; off >>= 1)
            mx = fmaxf(mx, __shfl_xor_sync(0xffffffff, mx, off));
        float s = 0.f;
        #pragma unroll
        for (int j = 0; j < 8; ++j) { q8[j] = __expf(q8[j] - mx); s += q8[j]; }
        #pragma unroll
        for (int off = 4; off > 0; off >>= 1)
            s += __shfl_xor_sync(0xffffffff, s, off);
        float inv = 1.f / s;

        int grow = bh * N_ + chunk * CTX_CHUNK + it * 32 + lr;
        bool mz;
        if (f32f)      mz = ((const float*)mask)[grow] != 0.f;
        else if (u8f)  mz = ((const unsigned char*)mask)[grow] != 0;
        else           mz = ((const int*)mask)[grow] != 0;

        if (it) __syncthreads();
        #pragma unroll
        for (int j = 0; j < 8; ++j) {
            float ez = __expf(k8[j]);
            ksl[j] += ez;                       // ksum over ALL rows (pre-mask)
            qs[lr][lc + j] = q8[j] * inv;
            ks[lr][lc + j] = mz ? 0.f : ez;     // unnormalized
        }
        __syncthreads();

        #pragma unroll
        for (int n = 0; n < 32; ++n) {
            float4 qa = *(float4*)&qs[n][d0];
            u64 kb0 = *(const u64*)&ks[n][e0];
            u64 kb1 = *(const u64*)&ks[n][e0 + 2];
            u64 p0 = pack_dup(qa.x), p1 = pack_dup(qa.y);
            u64 p2 = pack_dup(qa.z), p3 = pack_dup(qa.w);
            fma2(accp[0][0], p0, kb0); fma2(accp[0][1], p0, kb1);
            fma2(accp[1][0], p1, kb0); fma2(accp[1][1], p1, kb1);
            fma2(accp[2][0], p2, kb0); fma2(accp[2][1], p2, kb1);
            fma2(accp[3][0], p3, kb0); fma2(accp[3][1], p3, kb1);
        }
    }

    #pragma unroll
    for (int i = 0; i < 4; ++i) {
        float v0, v1, v2, v3;
        unpack2(v0, v1, accp[i][0]);
        unpack2(v2, v3, accp[i][1]);
        float* dst = &g_ctx[bh * 4096 + (d0 + i) * 64 + e0];
        atomicAdd(dst + 0, v0);
        atomicAdd(dst + 1, v1);
        atomicAdd(dst + 2, v2);
        atomicAdd(dst + 3, v3);
    }

    // ksum reduction: reuse qs smem
    __syncthreads();
    #pragma unroll
    for (int j = 0; j < 8; ++j) qs[lr][lc + j] = ksl[j];
    __syncthreads();
    if (t < 64) {
        float s = 0.f;
        #pragma unroll
        for (int r = 0; r < 32; ++r) s += qs[r][t];
        atomicAdd(&g_ksum[bh * 64 + t], s);
    }
}

// =============================================================================
// W2[b][h*64+d][c] = sum_e (ctxU[bh][d][e]/ksum[bh][e]) * Wout[h*64+e][c]
// grid (32 bh, 4 c-blocks of 128). Wout staged in smem (two 32-row halves).
// =============================================================================
__global__ __launch_bounds__(256) void w2_kernel(const float* __restrict__ Wout) {
    int bh = blockIdx.x, cb = blockIdx.y;
    int b = bh >> 3, h = bh & 7;
    __shared__ float cs[64][64];
    __shared__ float ws[32][128];
    int t = threadIdx.x;

    // load ctx with ksum divide: linear float4 idx = u*256+t -> col4 = t&15
    float4 kv = *(const float4*)&g_ksum[bh * 64 + (t & 15) * 4];
    const float4* cp4 = (const float4*)(g_ctx + bh * 4096);
    #pragma unroll
    for (int u = 0; u < 4; ++u) {
        float4 c4 = cp4[u * 256 + t];
        c4.x /= kv.x; c4.y /= kv.y; c4.z /= kv.z; c4.w /= kv.w;
        ((float4*)cs)[u * 256 + t] = c4;
    }

    int ty = t >> 4, tx = t & 15;
    int c0 = cb * 128 + tx * 8;
    const float* wbase = Wout + (size_t)(h * 64) * DIM_ + cb * 128;

    float acc[4][8];
    #pragma unroll
    for (int i = 0; i < 4; ++i)
        #pragma unroll
        for (int j = 0; j < 8; ++j) acc[i][j] = 0.f;

    #pragma unroll
    for (int half = 0; half < 2; ++half) {
        if (half) __syncthreads();
        // stage 32 rows of Wout: 1024 float4 / 256 threads = 4 each
        #pragma unroll
        for (int u = 0; u < 4; ++u) {
            int idx = u * 256 + t;
            int e = idx >> 5, c4 = idx & 31;
            *(float4*)&ws[e][c4 * 4] =
                *(const float4*)&wbase[(size_t)(half * 32 + e) * DIM_ + c4 * 4];
        }
        __syncthreads();

        #pragma unroll 4
        for (int e = 0; e < 32; ++e) {
            float4 w0 = *(const float4*)&ws[e][tx * 8];
            float4 w1 = *(const float4*)&ws[e][tx * 8 + 4];
            float wv[8] = {w0.x, w0.y, w0.z, w0.w, w1.x, w1.y, w1.z, w1.w};
            #pragma unroll
            for (int i = 0; i < 4; ++i) {
                float cv = cs[ty * 4 + i][half * 32 + e];
                #pragma unroll
                for (int j = 0; j < 8; ++j) acc[i][j] += cv * wv[j];
            }
        }
    }

    #pragma unroll
    for (int i = 0; i < 4; ++i) {
        size_t row = (size_t)b * DIM_ + h * 64 + ty * 4 + i;
        float* dst = g_w2 + row * DIM_ + c0;
        *(float4*)(dst)     = make_float4(acc[i][0], acc[i][1], acc[i][2], acc[i][3]);
        *(float4*)(dst + 4) = make_float4(acc[i][4], acc[i][5], acc[i][6], acc[i][7]);
    }
}

// =============================================================================
extern "C" void kernel_launch(void* const* d_in, const int* in_sizes, int n_in,
                              void* d_out, int out_size) {
    const float* x    = (const float*)d_in[0];
    const void*  mask = d_in[1];
    const float* Wqkv = (const float*)d_in[2];
    const float* Wout = (const float*)d_in[3];
    const float* bout = (const float*)d_in[4];
    float* out = (float*)d_out;

    void *pks, *pctx, *pfl, *pw3;
    cudaGetSymbolAddress(&pks,  g_ksum);
    cudaGetSymbolAddress(&pctx, g_ctx);
    cudaGetSymbolAddress(&pfl,  g_maskflags);
    cudaGetSymbolAddress(&pw3,  g_w3);
    cudaMemsetAsync(pks,  0, sizeof(float) * BH_ * DH_);
    cudaMemsetAsync(pctx, 0, sizeof(float) * BH_ * DH_ * DH_);
    cudaMemsetAsync(pfl,  0, 2 * sizeof(int));
    cudaMemsetAsync(pw3,  0, sizeof(float) * B_ * DIM_ * DIM_);

    gemm1_cp<<<dim3(QKN / 128, MROWS / 128), 256>>>(x, Wqkv);   // q,k only

    detect_mask_kernel<<<(BH_ * N_) / 1024, 256>>>((const unsigned char*)mask);
    ctx_fused_kernel<<<dim3(BH_, N_ / CTX_CHUNK), 256>>>(mask); // incl. ksum
    w2_kernel<<<dim3(BH_, 4), 256>>>(Wout);
    w3_kernel<<<dim3(4, 16, 4), 256>>>(Wqkv);

    gemm2_cp<<<dim3(DIM_ / 128, MROWS / 128), 256>>>(x, bout, out);
}

// round 13
// speedup vs baseline: 2.9824x; 1.0840x over previous
#include <cuda_runtime.h>
#include <math.h>
#include <stdint.h>

#define B_   4
#define N_   8192
#define DIM_ 512
#define H_   8
#define DH_  64
#define BH_  (B_*H_)          // 32
#define MROWS (B_*N_)         // 32768
#define QKVN  (3*DIM_)        // 1536

typedef unsigned long long u64;

// ---------------- scratch (device globals; no allocs allowed) ----------------
__device__ float g_ctx[BH_*DH_*DH_];   // [bh][d][e]  UNNORMALIZED (divide in w2)
__device__ float g_w2[(size_t)B_*DIM_*DIM_];   // [b][h*64+d][c] = (ctx_h/ksum) @ Wout_h
__device__ float g_w3[(size_t)B_*DIM_*DIM_];   // [b][k][c]      = Wv @ W2[b]
__device__ float g_ksum[BH_*DH_];      // [bh][e] = sum_n exp(k)
__device__ int   g_maskflags[2];

// ---------------- helpers ----------------
__device__ __forceinline__ uint32_t smem_u32(const void* p) {
    uint32_t a;
    asm("{ .reg .u64 t; cvta.to.shared.u64 t, %1; cvt.u32.u64 %0, t; }" : "=r"(a) : "l"(p));
    return a;
}
__device__ __forceinline__ void cp16(uint32_t dst, const void* src) {
    asm volatile("cp.async.ca.shared.global [%0], [%1], 16;" :: "r"(dst), "l"(src));
}
__device__ __forceinline__ void cp_commit() {
    asm volatile("cp.async.commit_group;" ::: "memory");
}
template<int N> __device__ __forceinline__ void cp_wait() {
    asm volatile("cp.async.wait_group %0;" :: "n"(N) : "memory");
}

// packed f32x2 helpers (FFMA2)
__device__ __forceinline__ u64 pack_dup(float a) {
    u64 p;
    asm("mov.b64 %0, {%1, %1};" : "=l"(p) : "f"(a));
    return p;
}
__device__ __forceinline__ void fma2(u64& d, u64 a, u64 b) {
    asm("fma.rn.f32x2 %0, %1, %2, %0;" : "+l"(d) : "l"(a), "l"(b));
}
__device__ __forceinline__ void unpack2(float& lo, float& hi, u64 p) {
    asm("mov.b64 {%0, %1}, %2;" : "=f"(lo), "=f"(hi) : "l"(p));
}

// smem geometry: A stage = 128 rows x (16 floats + 4 pad) = 10240 B
//                B stage = 16 rows x (128 floats + 4 pad) = 8448 B
#define A_STAGE 10240
#define B_BASE  20480
#define B_STAGE 8448
#define SMEM_TOT 37376

// =============================================================================
// Shared cp.async double-buffered f32x2 mainloop (generic B stride).
// =============================================================================
__device__ __forceinline__ void gemm_mainloop(u64 (&accp)[8][4], char* sm, uint32_t sb,
                                              const float* __restrict__ Ag, int AW,
                                              const float* __restrict__ Bg, int BW,
                                              int ch0, int nch) {
    const int tid = threadIdx.x;
    const int ty = tid >> 4, tx = tid & 15;
    const int m0 = ty * 8;

    #pragma unroll
    for (int i = 0; i < 8; ++i)
        #pragma unroll
        for (int j = 0; j < 4; ++j) accp[i][j] = 0ull;

    const int ar_ = tid >> 2,  ac_ = tid & 3;
    const int br_ = tid >> 5,  bc_ = tid & 31;

    auto issue = [&](int ch, int p) {
        uint32_t Ab = sb + p * A_STAGE;
        uint32_t Bb = sb + B_BASE + p * B_STAGE;
        int kc = (ch0 + ch) * 16;
        #pragma unroll
        for (int i = 0; i < 2; ++i) {
            int r = ar_ + i * 64;
            cp16(Ab + r * 80 + ac_ * 16, Ag + (size_t)r * AW + kc + ac_ * 4);
        }
        #pragma unroll
        for (int i = 0; i < 2; ++i) {
            int r = br_ + i * 8;
            cp16(Bb + r * 528 + bc_ * 16, Bg + (size_t)(kc + r) * BW + bc_ * 4);
        }
    };

    issue(0, 0);
    cp_commit();

    #pragma unroll 1
    for (int ch = 0; ch < nch; ++ch) {
        int p = ch & 1;
        cp_wait<0>();
        __syncthreads();
        if (ch < nch - 1) { issue(ch + 1, p ^ 1); cp_commit(); }

        const float* As = (const float*)(sm + p * A_STAGE);
        const char*  Bs = sm + B_BASE + p * B_STAGE;

        #pragma unroll
        for (int kk = 0; kk < 16; ++kk) {
            const char* brow = Bs + kk * 528 + tx * 32;
            u64 b0 = *(const u64*)(brow);
            u64 b1 = *(const u64*)(brow + 8);
            u64 b2 = *(const u64*)(brow + 16);
            u64 b3 = *(const u64*)(brow + 24);
            #pragma unroll
            for (int i = 0; i < 8; ++i) {
                u64 pa = pack_dup(As[(m0 + i) * 20 + kk]);
                fma2(accp[i][0], pa, b0);
                fma2(accp[i][1], pa, b1);
                fma2(accp[i][2], pa, b2);
                fma2(accp[i][3], pa, b3);
            }
        }
    }
}

// =============================================================================
// GEMM1 FUSED: per (b,h) CTA computes [q_h | k_h] = X_band @ W_gather, then
// q-softmax / k exp+mask / ksum / partial ctx — no q/k gmem round trip.
// grid (32 bh, 64 nbands of 128 rows).
// =============================================================================
__global__ __launch_bounds__(256, 2) void gemm1_fused(const float* __restrict__ X,
                                                      const float* __restrict__ W,
                                                      const void* __restrict__ mask) {
    __shared__ __align__(16) char sm[SMEM_TOT];
    uint32_t sb = smem_u32(sm);

    const int bh = blockIdx.x, nband = blockIdx.y;
    const int b = bh >> 3, h = bh & 7;
    const float* Ag = X + ((size_t)b * N_ + nband * 128) * DIM_;

    const int tid = threadIdx.x;
    const int ty = tid >> 4, tx = tid & 15;
    const int m0 = ty * 8;

    u64 accp[8][4];
    #pragma unroll
    for (int i = 0; i < 8; ++i)
        #pragma unroll
        for (int j = 0; j < 4; ++j) accp[i][j] = 0ull;

    const int ar_ = tid >> 2,  ac_ = tid & 3;
    const int br_ = tid >> 5,  bc_ = tid & 31;
    const int bcol = (bc_ < 16) ? (h * 64 + bc_ * 4)
                                : (512 + h * 64 + (bc_ - 16) * 4);

    auto issue = [&](int ch, int p) {
        uint32_t Ab = sb + p * A_STAGE;
        uint32_t Bb = sb + B_BASE + p * B_STAGE;
        int kc = ch * 16;
        #pragma unroll
        for (int i = 0; i < 2; ++i) {
            int r = ar_ + i * 64;
            cp16(Ab + r * 80 + ac_ * 16, Ag + (size_t)r * DIM_ + kc + ac_ * 4);
        }
        #pragma unroll
        for (int i = 0; i < 2; ++i) {
            int r = br_ + i * 8;
            cp16(Bb + r * 528 + bc_ * 16, W + (size_t)(kc + r) * QKVN + bcol);
        }
    };

    issue(0, 0);
    cp_commit();

    #pragma unroll 1
    for (int ch = 0; ch < 32; ++ch) {
        int p = ch & 1;
        cp_wait<0>();
        __syncthreads();
        if (ch < 31) { issue(ch + 1, p ^ 1); cp_commit(); }

        const float* As = (const float*)(sm + p * A_STAGE);
        const char*  Bs = sm + B_BASE + p * B_STAGE;

        #pragma unroll
        for (int kk = 0; kk < 16; ++kk) {
            const char* brow = Bs + kk * 528 + tx * 32;
            u64 b0 = *(const u64*)(brow);
            u64 b1 = *(const u64*)(brow + 8);
            u64 b2 = *(const u64*)(brow + 16);
            u64 b3 = *(const u64*)(brow + 24);
            #pragma unroll
            for (int i = 0; i < 8; ++i) {
                u64 pa = pack_dup(As[(m0 + i) * 20 + kk]);
                fma2(accp[i][0], pa, b0);
                fma2(accp[i][1], pa, b1);
                fma2(accp[i][2], pa, b2);
                fma2(accp[i][3], pa, b3);
            }
        }
    }

    float acc[8][8];
    #pragma unroll
    for (int i = 0; i < 8; ++i)
        #pragma unroll
        for (int j = 0; j < 4; ++j)
            unpack2(acc[i][2*j], acc[i][2*j+1], accp[i][j]);

    // ---- epilogue: q softmax (tx<8) / k exp+mask (tx>=8) ----
    const float SCALE = 0.125f;
    const int f32f = g_maskflags[0], u8f = g_maskflags[1];

    bool mzv[8];
    if (tx >= 8) {
        #pragma unroll
        for (int i = 0; i < 8; ++i) {
            int grow = bh * N_ + nband * 128 + ty * 8 + i;
            if (f32f)      mzv[i] = ((const float*)mask)[grow] != 0.f;
            else if (u8f)  mzv[i] = ((const unsigned char*)mask)[grow] != 0;
            else           mzv[i] = ((const int*)mask)[grow] != 0;
        }
    }

    float ksl[8];
    #pragma unroll
    for (int j = 0; j < 8; ++j) ksl[j] = 0.f;

    #pragma unroll
    for (int i = 0; i < 8; ++i) {
        // branchless 8-lane-group reductions (keeps warp converged for shfl)
        float sc[8];
        float lmx = -1e30f;
        #pragma unroll
        for (int j = 0; j < 8; ++j) { sc[j] = acc[i][j] * SCALE; lmx = fmaxf(lmx, sc[j]); }
        #pragma unroll
        for (int off = 4; off > 0; off >>= 1)
            lmx = fmaxf(lmx, __shfl_xor_sync(0xffffffff, lmx, off));
        float lsum = 0.f;
        #pragma unroll
        for (int j = 0; j < 8; ++j) { sc[j] = __expf(sc[j] - lmx); lsum += sc[j]; }
        #pragma unroll
        for (int off = 4; off > 0; off >>= 1)
            lsum += __shfl_xor_sync(0xffffffff, lsum, off);
        float inv = 1.f / lsum;

        if (tx < 8) {
            #pragma unroll
            for (int j = 0; j < 8; ++j) acc[i][j] = sc[j] * inv;
        } else {
            bool mz = mzv[i];
            #pragma unroll
            for (int j = 0; j < 8; ++j) {
                float ez = __expf(acc[i][j]);
                ksl[j] += ez;                    // ksum pre-mask
                acc[i][j] = mz ? 0.f : ez;
            }
        }
    }

    // ---- ksum reduction (red at sm+32768, 4KB) ----
    float* red = (float*)(sm + 32768);
    __syncthreads();                 // mainloop smem free
    if (tx >= 8) {
        #pragma unroll
        for (int j = 0; j < 8; ++j) red[ty * 64 + (tx - 8) * 8 + j] = ksl[j];
    }
    __syncthreads();
    if (tid < 64) {
        float s = 0.f;
        #pragma unroll
        for (int r = 0; r < 16; ++r) s += red[r * 64 + tid];
        atomicAdd(&g_ksum[bh * 64 + tid], s);
    }

    // ---- partial ctx: two 64-row halves staged in smem ----
    float* qsm = (float*)sm;             // [64][64]
    float* ksm = (float*)(sm + 16384);   // [64][64]
    const int d0 = (tid >> 4) * 4, e0 = (tid & 15) * 4;

    u64 cacc[4][2];
    #pragma unroll
    for (int i = 0; i < 4; ++i) { cacc[i][0] = 0ull; cacc[i][1] = 0ull; }

    #pragma unroll
    for (int half = 0; half < 2; ++half) {
        __syncthreads();
        if ((ty >> 3) == half) {
            int lty = ty & 7;
            if (tx < 8) {
                #pragma unroll
                for (int i = 0; i < 8; ++i)
                    #pragma unroll
                    for (int j = 0; j < 8; ++j)
                        qsm[(lty * 8 + i) * 64 + tx * 8 + j] = acc[i][j];
            } else {
                #pragma unroll
                for (int i = 0; i < 8; ++i)
                    #pragma unroll
                    for (int j = 0; j < 8; ++j)
                        ksm[(lty * 8 + i) * 64 + (tx - 8) * 8 + j] = acc[i][j];
            }
        }
        __syncthreads();

        #pragma unroll 4
        for (int r = 0; r < 64; ++r) {
            float4 qa = *(const float4*)&qsm[r * 64 + d0];
            u64 kb0 = *(const u64*)&ksm[r * 64 + e0];
            u64 kb1 = *(const u64*)&ksm[r * 64 + e0 + 2];
            u64 p0 = pack_dup(qa.x), p1 = pack_dup(qa.y);
            u64 p2 = pack_dup(qa.z), p3 = pack_dup(qa.w);
            fma2(cacc[0][0], p0, kb0); fma2(cacc[0][1], p0, kb1);
            fma2(cacc[1][0], p1, kb0); fma2(cacc[1][1], p1, kb1);
            fma2(cacc[2][0], p2, kb0); fma2(cacc[2][1], p2, kb1);
            fma2(cacc[3][0], p3, kb0); fma2(cacc[3][1], p3, kb1);
        }
    }

    #pragma unroll
    for (int i = 0; i < 4; ++i) {
        float v0, v1, v2, v3;
        unpack2(v0, v1, cacc[i][0]);
        unpack2(v2, v3, cacc[i][1]);
        float* dst = &g_ctx[bh * 4096 + (d0 + i) * 64 + e0];
        atomicAdd(dst + 0, v0);
        atomicAdd(dst + 1, v1);
        atomicAdd(dst + 2, v2);
        atomicAdd(dst + 3, v3);
    }
}

// =============================================================================
// W3[b] += Wv_slice @ W2[b]  (K-split 4, atomicAdd). grid (4, 16, 4).
// =============================================================================
__global__ __launch_bounds__(256, 2) void w3_kernel(const float* __restrict__ Wqkv) {
    __shared__ __align__(16) char sm[SMEM_TOT];
    uint32_t sb = smem_u32(sm);

    const int nBase = blockIdx.x * 128;
    const int mBase = blockIdx.y * 128;
    const int b     = mBase >> 9;
    const int kr0   = mBase & 511;
    const int ks    = blockIdx.z;

    u64 accp[8][4];
    gemm_mainloop(accp, sm, sb,
                  Wqkv + (size_t)kr0 * QKVN + 1024, QKVN,
                  g_w2 + (size_t)b * DIM_ * DIM_ + nBase, DIM_,
                  ks * 8, 8);

    float acc[8][8];
    #pragma unroll
    for (int i = 0; i < 8; ++i)
        #pragma unroll
        for (int j = 0; j < 4; ++j)
            unpack2(acc[i][2*j], acc[i][2*j+1], accp[i][j]);

    const int tid = threadIdx.x;
    const int ty = tid >> 4, tx = tid & 15;
    const int m0 = ty * 8, n0 = tx * 8;

    #pragma unroll
    for (int i = 0; i < 8; ++i) {
        float* dst = g_w3 + (size_t)b * DIM_ * DIM_ + (size_t)(kr0 + m0 + i) * DIM_ + nBase + n0;
        #pragma unroll
        for (int j = 0; j < 8; ++j) atomicAdd(dst + j, acc[i][j]);
    }
}

// =============================================================================
// GEMM2: out = X @ W3[b] + bout.  grid (4, 256).
// =============================================================================
__global__ __launch_bounds__(256, 2) void gemm2_cp(const float* __restrict__ X,
                                                   const float* __restrict__ bias,
                                                   float* __restrict__ out) {
    __shared__ __align__(16) char sm[SMEM_TOT];
    uint32_t sb = smem_u32(sm);

    const int nBase = blockIdx.x * 128;
    const int mBase = blockIdx.y * 128;
    const int b     = mBase >> 13;

    u64 accp[8][4];
    gemm_mainloop(accp, sm, sb,
                  X + (size_t)mBase * DIM_, DIM_,
                  g_w3 + (size_t)b * DIM_ * DIM_ + nBase, DIM_, 0, 32);

    float acc[8][8];
    #pragma unroll
    for (int i = 0; i < 8; ++i)
        #pragma unroll
        for (int j = 0; j < 4; ++j)
            unpack2(acc[i][2*j], acc[i][2*j+1], accp[i][j]);

    const int tid = threadIdx.x;
    const int ty = tid >> 4, tx = tid & 15;
    const int m0 = ty * 8, n0 = tx * 8;

    #pragma unroll
    for (int i = 0; i < 8; ++i) {
        int gm = mBase + m0 + i;
        #pragma unroll
        for (int j = 0; j < 8; j += 4) {
            int gn = nBase + n0 + j;
            float4 bv = *(const float4*)&bias[gn];
            float4 o = make_float4(acc[i][j] + bv.x, acc[i][j+1] + bv.y,
                                   acc[i][j+2] + bv.z, acc[i][j+3] + bv.w);
            *(float4*)&out[(size_t)gm * DIM_ + gn] = o;
        }
    }
}

// =============================================================================
// Mask dtype detection (bool may be serialized as u8 / i32 / f32).
// =============================================================================
__global__ __launch_bounds__(256) void detect_mask_kernel(const unsigned char* __restrict__ m) {
    int i = blockIdx.x * 256 + threadIdx.x;
    uchar4 v = ((const uchar4*)m)[i];
    bool f32sig = (v.w == 0x3f);
    bool offnz  = (v.y | v.z | v.w) != 0;
    unsigned b1 = __ballot_sync(0xffffffff, f32sig);
    unsigned b2 = __ballot_sync(0xffffffff, offnz);
    if ((threadIdx.x & 31) == 0) {
        if (b1) atomicOr(&g_maskflags[0], 1);
        if (b2) atomicOr(&g_maskflags[1], 1);
    }
}

// =============================================================================
// W2[b][h*64+d][c] = sum_e (ctxU[bh][d][e]/ksum[bh][e]) * Wout[h*64+e][c]
// grid (32 bh, 4 c-blocks of 128). Wout staged in smem (two 32-row halves).
// =============================================================================
__global__ __launch_bounds__(256) void w2_kernel(const float* __restrict__ Wout) {
    int bh = blockIdx.x, cb = blockIdx.y;
    int b = bh >> 3, h = bh & 7;
    __shared__ float cs[64][64];
    __shared__ float ws[32][128];
    int t = threadIdx.x;

    float4 kv = *(const float4*)&g_ksum[bh * 64 + (t & 15) * 4];
    const float4* cp4 = (const float4*)(g_ctx + bh * 4096);
    #pragma unroll
    for (int u = 0; u < 4; ++u) {
        float4 c4 = cp4[u * 256 + t];
        c4.x /= kv.x; c4.y /= kv.y; c4.z /= kv.z; c4.w /= kv.w;
        ((float4*)cs)[u * 256 + t] = c4;
    }

    int ty = t >> 4, tx = t & 15;
    int c0 = cb * 128 + tx * 8;
    const float* wbase = Wout + (size_t)(h * 64) * DIM_ + cb * 128;

    float acc[4][8];
    #pragma unroll
    for (int i = 0; i < 4; ++i)
        #pragma unroll
        for (int j = 0; j < 8; ++j) acc[i][j] = 0.f;

    #pragma unroll
    for (int half = 0; half < 2; ++half) {
        if (half) __syncthreads();
        #pragma unroll
        for (int u = 0; u < 4; ++u) {
            int idx = u * 256 + t;
            int e = idx >> 5, c4 = idx & 31;
            *(float4*)&ws[e][c4 * 4] =
                *(const float4*)&wbase[(size_t)(half * 32 + e) * DIM_ + c4 * 4];
        }
        __syncthreads();

        #pragma unroll 4
        for (int e = 0; e < 32; ++e) {
            float4 w0 = *(const float4*)&ws[e][tx * 8];
            float4 w1 = *(const float4*)&ws[e][tx * 8 + 4];
            float wv[8] = {w0.x, w0.y, w0.z, w0.w, w1.x, w1.y, w1.z, w1.w};
            #pragma unroll
            for (int i = 0; i < 4; ++i) {
                float cv = cs[ty * 4 + i][half * 32 + e];
                #pragma unroll
                for (int j = 0; j < 8; ++j) acc[i][j] += cv * wv[j];
            }
        }
    }

    #pragma unroll
    for (int i = 0; i < 4; ++i) {
        size_t row = (size_t)b * DIM_ + h * 64 + ty * 4 + i;
        float* dst = g_w2 + row * DIM_ + c0;
        *(float4*)(dst)     = make_float4(acc[i][0], acc[i][1], acc[i][2], acc[i][3]);
        *(float4*)(dst + 4) = make_float4(acc[i][4], acc[i][5], acc[i][6], acc[i][7]);
    }
}

// =============================================================================
extern "C" void kernel_launch(void* const* d_in, const int* in_sizes, int n_in,
                              void* d_out, int out_size) {
    const float* x    = (const float*)d_in[0];
    const void*  mask = d_in[1];
    const float* Wqkv = (const float*)d_in[2];
    const float* Wout = (const float*)d_in[3];
    const float* bout = (const float*)d_in[4];
    float* out = (float*)d_out;

    void *pks, *pctx, *pfl, *pw3;
    cudaGetSymbolAddress(&pks,  g_ksum);
    cudaGetSymbolAddress(&pctx, g_ctx);
    cudaGetSymbolAddress(&pfl,  g_maskflags);
    cudaGetSymbolAddress(&pw3,  g_w3);
    cudaMemsetAsync(pks,  0, sizeof(float) * BH_ * DH_);
    cudaMemsetAsync(pctx, 0, sizeof(float) * BH_ * DH_ * DH_);
    cudaMemsetAsync(pfl,  0, 2 * sizeof(int));
    cudaMemsetAsync(pw3,  0, sizeof(float) * B_ * DIM_ * DIM_);

    detect_mask_kernel<<<(BH_ * N_) / 1024, 256>>>((const unsigned char*)mask);

    gemm1_fused<<<dim3(BH_, N_ / 128), 256>>>(x, Wqkv, mask);   // q,k + ctx + ksum

    w2_kernel<<<dim3(BH_, 4), 256>>>(Wout);
    w3_kernel<<<dim3(4, 16, 4), 256>>>(Wqkv);

    gemm2_cp<<<dim3(DIM_ / 128, MROWS / 128), 256>>>(x, bout, out);
}

// round 14
// speedup vs baseline: 2.9948x; 1.0041x over previous
#include <cuda_runtime.h>
#include <math.h>
#include <stdint.h>

#define B_   4
#define N_   8192
#define DIM_ 512
#define H_   8
#define DH_  64
#define BH_  (B_*H_)          // 32
#define MROWS (B_*N_)         // 32768
#define QKVN  (3*DIM_)        // 1536

typedef unsigned long long u64;

// ---------------- scratch (device globals; no allocs allowed) ----------------
__device__ float g_ctx[BH_*DH_*DH_];   // [bh][d][e]  UNNORMALIZED (divide in w2)
__device__ float g_w2[(size_t)B_*DIM_*DIM_];   // [b][h*64+d][c] = (ctx_h/ksum) @ Wout_h
__device__ float g_w3[(size_t)B_*DIM_*DIM_];   // [b][k][c]      = Wv @ W2[b]
__device__ float g_ksum[BH_*DH_];      // [bh][e] = sum_n exp(k)
__device__ int   g_maskflags[2];

// ---------------- helpers ----------------
__device__ __forceinline__ uint32_t smem_u32(const void* p) {
    uint32_t a;
    asm("{ .reg .u64 t; cvta.to.shared.u64 t, %1; cvt.u32.u64 %0, t; }" : "=r"(a) : "l"(p));
    return a;
}
__device__ __forceinline__ void cp16(uint32_t dst, const void* src) {
    asm volatile("cp.async.ca.shared.global [%0], [%1], 16;" :: "r"(dst), "l"(src));
}
__device__ __forceinline__ void cp_commit() {
    asm volatile("cp.async.commit_group;" ::: "memory");
}
template<int N> __device__ __forceinline__ void cp_wait() {
    asm volatile("cp.async.wait_group %0;" :: "n"(N) : "memory");
}

// packed f32x2 helpers (FFMA2)
__device__ __forceinline__ u64 pack_dup(float a) {
    u64 p;
    asm("mov.b64 %0, {%1, %1};" : "=l"(p) : "f"(a));
    return p;
}
__device__ __forceinline__ void fma2(u64& d, u64 a, u64 b) {
    asm("fma.rn.f32x2 %0, %1, %2, %0;" : "+l"(d) : "l"(a), "l"(b));
}
__device__ __forceinline__ void unpack2(float& lo, float& hi, u64 p) {
    asm("mov.b64 {%0, %1}, %2;" : "=f"(lo), "=f"(hi) : "l"(p));
}

// smem geometry: A stage = 128 rows x (16 floats + 4 pad) = 10240 B
//                B stage = 16 rows x (128 floats + 4 pad) = 8448 B
#define A_STAGE 10240
#define B_BASE  20480
#define B_STAGE 8448
#define SMEM_TOT 37376

// =============================================================================
// Shared cp.async double-buffered f32x2 mainloop (generic B stride).
// =============================================================================
__device__ __forceinline__ void gemm_mainloop(u64 (&accp)[8][4], char* sm, uint32_t sb,
                                              const float* __restrict__ Ag, int AW,
                                              const float* __restrict__ Bg, int BW,
                                              int ch0, int nch) {
    const int tid = threadIdx.x;
    const int ty = tid >> 4, tx = tid & 15;
    const int m0 = ty * 8;

    #pragma unroll
    for (int i = 0; i < 8; ++i)
        #pragma unroll
        for (int j = 0; j < 4; ++j) accp[i][j] = 0ull;

    const int ar_ = tid >> 2,  ac_ = tid & 3;
    const int br_ = tid >> 5,  bc_ = tid & 31;

    auto issue = [&](int ch, int p) {
        uint32_t Ab = sb + p * A_STAGE;
        uint32_t Bb = sb + B_BASE + p * B_STAGE;
        int kc = (ch0 + ch) * 16;
        #pragma unroll
        for (int i = 0; i < 2; ++i) {
            int r = ar_ + i * 64;
            cp16(Ab + r * 80 + ac_ * 16, Ag + (size_t)r * AW + kc + ac_ * 4);
        }
        #pragma unroll
        for (int i = 0; i < 2; ++i) {
            int r = br_ + i * 8;
            cp16(Bb + r * 528 + bc_ * 16, Bg + (size_t)(kc + r) * BW + bc_ * 4);
        }
    };

    issue(0, 0);
    cp_commit();

    #pragma unroll 1
    for (int ch = 0; ch < nch; ++ch) {
        int p = ch & 1;
        cp_wait<0>();
        __syncthreads();
        if (ch < nch - 1) { issue(ch + 1, p ^ 1); cp_commit(); }

        const float* As = (const float*)(sm + p * A_STAGE);
        const char*  Bs = sm + B_BASE + p * B_STAGE;

        #pragma unroll
        for (int kk = 0; kk < 16; ++kk) {
            const char* brow = Bs + kk * 528 + tx * 32;
            u64 b0 = *(const u64*)(brow);
            u64 b1 = *(const u64*)(brow + 8);
            u64 b2 = *(const u64*)(brow + 16);
            u64 b3 = *(const u64*)(brow + 24);
            #pragma unroll
            for (int i = 0; i < 8; ++i) {
                u64 pa = pack_dup(As[(m0 + i) * 20 + kk]);
                fma2(accp[i][0], pa, b0);
                fma2(accp[i][1], pa, b1);
                fma2(accp[i][2], pa, b2);
                fma2(accp[i][3], pa, b3);
            }
        }
    }
}

// =============================================================================
// GEMM1 FUSED: per (b,h) CTA computes [q_h | k_h] = X_band @ W_gather, then
// q-softmax / k exp+mask / ksum / partial ctx — no q/k gmem round trip.
// grid (32 bh, 64 nbands of 128 rows).
// =============================================================================
__global__ __launch_bounds__(256, 2) void gemm1_fused(const float* __restrict__ X,
                                                      const float* __restrict__ W,
                                                      const void* __restrict__ mask) {
    __shared__ __align__(16) char sm[SMEM_TOT];
    uint32_t sb = smem_u32(sm);

    const int bh = blockIdx.x, nband = blockIdx.y;
    const int b = bh >> 3, h = bh & 7;
    const float* Ag = X + ((size_t)b * N_ + nband * 128) * DIM_;

    const int tid = threadIdx.x;
    const int ty = tid >> 4, tx = tid & 15;
    const int m0 = ty * 8;

    u64 accp[8][4];
    #pragma unroll
    for (int i = 0; i < 8; ++i)
        #pragma unroll
        for (int j = 0; j < 4; ++j) accp[i][j] = 0ull;

    const int ar_ = tid >> 2,  ac_ = tid & 3;
    const int br_ = tid >> 5,  bc_ = tid & 31;
    const int bcol = (bc_ < 16) ? (h * 64 + bc_ * 4)
                                : (512 + h * 64 + (bc_ - 16) * 4);

    auto issue = [&](int ch, int p) {
        uint32_t Ab = sb + p * A_STAGE;
        uint32_t Bb = sb + B_BASE + p * B_STAGE;
        int kc = ch * 16;
        #pragma unroll
        for (int i = 0; i < 2; ++i) {
            int r = ar_ + i * 64;
            cp16(Ab + r * 80 + ac_ * 16, Ag + (size_t)r * DIM_ + kc + ac_ * 4);
        }
        #pragma unroll
        for (int i = 0; i < 2; ++i) {
            int r = br_ + i * 8;
            cp16(Bb + r * 528 + bc_ * 16, W + (size_t)(kc + r) * QKVN + bcol);
        }
    };

    issue(0, 0);
    cp_commit();

    #pragma unroll 1
    for (int ch = 0; ch < 32; ++ch) {
        int p = ch & 1;
        cp_wait<0>();
        __syncthreads();
        if (ch < 31) { issue(ch + 1, p ^ 1); cp_commit(); }

        const float* As = (const float*)(sm + p * A_STAGE);
        const char*  Bs = sm + B_BASE + p * B_STAGE;

        #pragma unroll
        for (int kk = 0; kk < 16; ++kk) {
            const char* brow = Bs + kk * 528 + tx * 32;
            u64 b0 = *(const u64*)(brow);
            u64 b1 = *(const u64*)(brow + 8);
            u64 b2 = *(const u64*)(brow + 16);
            u64 b3 = *(const u64*)(brow + 24);
            #pragma unroll
            for (int i = 0; i < 8; ++i) {
                u64 pa = pack_dup(As[(m0 + i) * 20 + kk]);
                fma2(accp[i][0], pa, b0);
                fma2(accp[i][1], pa, b1);
                fma2(accp[i][2], pa, b2);
                fma2(accp[i][3], pa, b3);
            }
        }
    }

    float acc[8][8];
    #pragma unroll
    for (int i = 0; i < 8; ++i)
        #pragma unroll
        for (int j = 0; j < 4; ++j)
            unpack2(acc[i][2*j], acc[i][2*j+1], accp[i][j]);

    // ---- epilogue: q softmax (tx<8) / k exp+mask (tx>=8) ----
    // no max-subtraction: exp(a)/sum(exp(a)) — q*SCALE is small, overflow-safe
    const float SCALE = 0.125f;
    const int f32f = g_maskflags[0], u8f = g_maskflags[1];

    bool mzv[8];
    if (tx >= 8) {
        #pragma unroll
        for (int i = 0; i < 8; ++i) {
            int grow = bh * N_ + nband * 128 + ty * 8 + i;
            if (f32f)      mzv[i] = ((const float*)mask)[grow] != 0.f;
            else if (u8f)  mzv[i] = ((const unsigned char*)mask)[grow] != 0;
            else           mzv[i] = ((const int*)mask)[grow] != 0;
        }
    }

    float ksl[8];
    #pragma unroll
    for (int j = 0; j < 8; ++j) ksl[j] = 0.f;

    #pragma unroll
    for (int i = 0; i < 8; ++i) {
        float sc[8];
        float lsum = 0.f;
        #pragma unroll
        for (int j = 0; j < 8; ++j) { sc[j] = __expf(acc[i][j] * SCALE); lsum += sc[j]; }
        #pragma unroll
        for (int off = 4; off > 0; off >>= 1)
            lsum += __shfl_xor_sync(0xffffffff, lsum, off);
        float inv = 1.f / lsum;

        if (tx < 8) {
            #pragma unroll
            for (int j = 0; j < 8; ++j) acc[i][j] = sc[j] * inv;
        } else {
            bool mz = mzv[i];
            #pragma unroll
            for (int j = 0; j < 8; ++j) {
                float ez = __expf(acc[i][j]);
                ksl[j] += ez;                    // ksum pre-mask
                acc[i][j] = mz ? 0.f : ez;
            }
        }
    }

    // ---- ksum reduction (red at sm+32768, 4KB) ----
    float* red = (float*)(sm + 32768);
    __syncthreads();                 // mainloop smem free
    if (tx >= 8) {
        #pragma unroll
        for (int j = 0; j < 8; ++j) red[ty * 64 + (tx - 8) * 8 + j] = ksl[j];
    }
    __syncthreads();
    if (tid < 64) {
        float s = 0.f;
        #pragma unroll
        for (int r = 0; r < 16; ++r) s += red[r * 64 + tid];
        atomicAdd(&g_ksum[bh * 64 + tid], s);
    }

    // ---- partial ctx: two 64-row halves staged in smem ----
    float* qsm = (float*)sm;             // [64][64]
    float* ksm = (float*)(sm + 16384);   // [64][64]
    const int d0 = (tid >> 4) * 4, e0 = (tid & 15) * 4;

    u64 cacc[4][2];
    #pragma unroll
    for (int i = 0; i < 4; ++i) { cacc[i][0] = 0ull; cacc[i][1] = 0ull; }

    #pragma unroll
    for (int half = 0; half < 2; ++half) {
        __syncthreads();
        if ((ty >> 3) == half) {
            int lty = ty & 7;
            if (tx < 8) {
                #pragma unroll
                for (int i = 0; i < 8; ++i)
                    #pragma unroll
                    for (int j = 0; j < 8; ++j)
                        qsm[(lty * 8 + i) * 64 + tx * 8 + j] = acc[i][j];
            } else {
                #pragma unroll
                for (int i = 0; i < 8; ++i)
                    #pragma unroll
                    for (int j = 0; j < 8; ++j)
                        ksm[(lty * 8 + i) * 64 + (tx - 8) * 8 + j] = acc[i][j];
            }
        }
        __syncthreads();

        #pragma unroll 4
        for (int r = 0; r < 64; ++r) {
            float4 qa = *(const float4*)&qsm[r * 64 + d0];
            u64 kb0 = *(const u64*)&ksm[r * 64 + e0];
            u64 kb1 = *(const u64*)&ksm[r * 64 + e0 + 2];
            u64 p0 = pack_dup(qa.x), p1 = pack_dup(qa.y);
            u64 p2 = pack_dup(qa.z), p3 = pack_dup(qa.w);
            fma2(cacc[0][0], p0, kb0); fma2(cacc[0][1], p0, kb1);
            fma2(cacc[1][0], p1, kb0); fma2(cacc[1][1], p1, kb1);
            fma2(cacc[2][0], p2, kb0); fma2(cacc[2][1], p2, kb1);
            fma2(cacc[3][0], p3, kb0); fma2(cacc[3][1], p3, kb1);
        }
    }

    #pragma unroll
    for (int i = 0; i < 4; ++i) {
        float v0, v1, v2, v3;
        unpack2(v0, v1, cacc[i][0]);
        unpack2(v2, v3, cacc[i][1]);
        float* dst = &g_ctx[bh * 4096 + (d0 + i) * 64 + e0];
        atomicAdd(dst + 0, v0);
        atomicAdd(dst + 1, v1);
        atomicAdd(dst + 2, v2);
        atomicAdd(dst + 3, v3);
    }
}

// =============================================================================
// W3[b] += Wv_slice @ W2[b]  (K-split 2, atomicAdd). grid (4, 16, 2).
// =============================================================================
__global__ __launch_bounds__(256, 2) void w3_kernel(const float* __restrict__ Wqkv) {
    __shared__ __align__(16) char sm[SMEM_TOT];
    uint32_t sb = smem_u32(sm);

    const int nBase = blockIdx.x * 128;
    const int mBase = blockIdx.y * 128;
    const int b     = mBase >> 9;
    const int kr0   = mBase & 511;
    const int ks    = blockIdx.z;                // 0..1

    u64 accp[8][4];
    gemm_mainloop(accp, sm, sb,
                  Wqkv + (size_t)kr0 * QKVN + 1024, QKVN,
                  g_w2 + (size_t)b * DIM_ * DIM_ + nBase, DIM_,
                  ks * 16, 16);

    float acc[8][8];
    #pragma unroll
    for (int i = 0; i < 8; ++i)
        #pragma unroll
        for (int j = 0; j < 4; ++j)
            unpack2(acc[i][2*j], acc[i][2*j+1], accp[i][j]);

    const int tid = threadIdx.x;
    const int ty = tid >> 4, tx = tid & 15;
    const int m0 = ty * 8, n0 = tx * 8;

    #pragma unroll
    for (int i = 0; i < 8; ++i) {
        float* dst = g_w3 + (size_t)b * DIM_ * DIM_ + (size_t)(kr0 + m0 + i) * DIM_ + nBase + n0;
        #pragma unroll
        for (int j = 0; j < 8; ++j) atomicAdd(dst + j, acc[i][j]);
    }
}

// =============================================================================
// GEMM2: out = X @ W3[b] + bout.  grid (4, 256).
// =============================================================================
__global__ __launch_bounds__(256, 2) void gemm2_cp(const float* __restrict__ X,
                                                   const float* __restrict__ bias,
                                                   float* __restrict__ out) {
    __shared__ __align__(16) char sm[SMEM_TOT];
    uint32_t sb = smem_u32(sm);

    const int nBase = blockIdx.x * 128;
    const int mBase = blockIdx.y * 128;
    const int b     = mBase >> 13;

    u64 accp[8][4];
    gemm_mainloop(accp, sm, sb,
                  X + (size_t)mBase * DIM_, DIM_,
                  g_w3 + (size_t)b * DIM_ * DIM_ + nBase, DIM_, 0, 32);

    float acc[8][8];
    #pragma unroll
    for (int i = 0; i < 8; ++i)
        #pragma unroll
        for (int j = 0; j < 4; ++j)
            unpack2(acc[i][2*j], acc[i][2*j+1], accp[i][j]);

    const int tid = threadIdx.x;
    const int ty = tid >> 4, tx = tid & 15;
    const int m0 = ty * 8, n0 = tx * 8;

    #pragma unroll
    for (int i = 0; i < 8; ++i) {
        int gm = mBase + m0 + i;
        #pragma unroll
        for (int j = 0; j < 8; j += 4) {
            int gn = nBase + n0 + j;
            float4 bv = *(const float4*)&bias[gn];
            float4 o = make_float4(acc[i][j] + bv.x, acc[i][j+1] + bv.y,
                                   acc[i][j+2] + bv.z, acc[i][j+3] + bv.w);
            *(float4*)&out[(size_t)gm * DIM_ + gn] = o;
        }
    }
}

// =============================================================================
// Mask dtype detection (bool may be serialized as u8 / i32 / f32).
// =============================================================================
__global__ __launch_bounds__(256) void detect_mask_kernel(const unsigned char* __restrict__ m) {
    int i = blockIdx.x * 256 + threadIdx.x;
    uchar4 v = ((const uchar4*)m)[i];
    bool f32sig = (v.w == 0x3f);
    bool offnz  = (v.y | v.z | v.w) != 0;
    unsigned b1 = __ballot_sync(0xffffffff, f32sig);
    unsigned b2 = __ballot_sync(0xffffffff, offnz);
    if ((threadIdx.x & 31) == 0) {
        if (b1) atomicOr(&g_maskflags[0], 1);
        if (b2) atomicOr(&g_maskflags[1], 1);
    }
}

// =============================================================================
// W2[b][h*64+d][c] = sum_e (ctxU[bh][d][e]/ksum[bh][e]) * Wout[h*64+e][c]
// grid (32 bh, 4 c-blocks of 128). Wout staged in smem (two 32-row halves).
// =============================================================================
__global__ __launch_bounds__(256) void w2_kernel(const float* __restrict__ Wout) {
    int bh = blockIdx.x, cb = blockIdx.y;
    int b = bh >> 3, h = bh & 7;
    __shared__ float cs[64][64];
    __shared__ float ws[32][128];
    int t = threadIdx.x;

    float4 kv = *(const float4*)&g_ksum[bh * 64 + (t & 15) * 4];
    const float4* cp4 = (const float4*)(g_ctx + bh * 4096);
    #pragma unroll
    for (int u = 0; u < 4; ++u) {
        float4 c4 = cp4[u * 256 + t];
        c4.x /= kv.x; c4.y /= kv.y; c4.z /= kv.z; c4.w /= kv.w;
        ((float4*)cs)[u * 256 + t] = c4;
    }

    int ty = t >> 4, tx = t & 15;
    int c0 = cb * 128 + tx * 8;
    const float* wbase = Wout + (size_t)(h * 64) * DIM_ + cb * 128;

    float acc[4][8];
    #pragma unroll
    for (int i = 0; i < 4; ++i)
        #pragma unroll
        for (int j = 0; j < 8; ++j) acc[i][j] = 0.f;

    #pragma unroll
    for (int half = 0; half < 2; ++half) {
        if (half) __syncthreads();
        #pragma unroll
        for (int u = 0; u < 4; ++u) {
            int idx = u * 256 + t;
            int e = idx >> 5, c4 = idx & 31;
            *(float4*)&ws[e][c4 * 4] =
                *(const float4*)&wbase[(size_t)(half * 32 + e) * DIM_ + c4 * 4];
        }
        __syncthreads();

        #pragma unroll 4
        for (int e = 0; e < 32; ++e) {
            float4 w0 = *(const float4*)&ws[e][tx * 8];
            float4 w1 = *(const float4*)&ws[e][tx * 8 + 4];
            float wv[8] = {w0.x, w0.y, w0.z, w0.w, w1.x, w1.y, w1.z, w1.w};
            #pragma unroll
            for (int i = 0; i < 4; ++i) {
                float cv = cs[ty * 4 + i][half * 32 + e];
                #pragma unroll
                for (int j = 0; j < 8; ++j) acc[i][j] += cv * wv[j];
            }
        }
    }

    #pragma unroll
    for (int i = 0; i < 4; ++i) {
        size_t row = (size_t)b * DIM_ + h * 64 + ty * 4 + i;
        float* dst = g_w2 + row * DIM_ + c0;
        *(float4*)(dst)     = make_float4(acc[i][0], acc[i][1], acc[i][2], acc[i][3]);
        *(float4*)(dst + 4) = make_float4(acc[i][4], acc[i][5], acc[i][6], acc[i][7]);
    }
}

// =============================================================================
extern "C" void kernel_launch(void* const* d_in, const int* in_sizes, int n_in,
                              void* d_out, int out_size) {
    const float* x    = (const float*)d_in[0];
    const void*  mask = d_in[1];
    const float* Wqkv = (const float*)d_in[2];
    const float* Wout = (const float*)d_in[3];
    const float* bout = (const float*)d_in[4];
    float* out = (float*)d_out;

    void *pks, *pctx, *pfl, *pw3;
    cudaGetSymbolAddress(&pks,  g_ksum);
    cudaGetSymbolAddress(&pctx, g_ctx);
    cudaGetSymbolAddress(&pfl,  g_maskflags);
    cudaGetSymbolAddress(&pw3,  g_w3);
    cudaMemsetAsync(pks,  0, sizeof(float) * BH_ * DH_);
    cudaMemsetAsync(pctx, 0, sizeof(float) * BH_ * DH_ * DH_);
    cudaMemsetAsync(pfl,  0, 2 * sizeof(int));
    cudaMemsetAsync(pw3,  0, sizeof(float) * B_ * DIM_ * DIM_);

    detect_mask_kernel<<<(BH_ * N_) / 1024, 256>>>((const unsigned char*)mask);

    gemm1_fused<<<dim3(BH_, N_ / 128), 256>>>(x, Wqkv, mask);   // q,k + ctx + ksum

    w2_kernel<<<dim3(BH_, 4), 256>>>(Wout);
    w3_kernel<<<dim3(4, 16, 2), 256>>>(Wqkv);

    gemm2_cp<<<dim3(DIM_ / 128, MROWS / 128), 256>>>(x, bout, out);
}